// round 12
// baseline (speedup 1.0000x reference)
#include <cuda_runtime.h>
#include <cuda.h>
#include <cuda_bf16.h>
#include <cuda_fp16.h>
#include <math.h>
#include <stdint.h>

#define N_NODES 100000
#define N_EDGES 20000
#define NNZ     1600000
#define NCHUNK  5           // 5 chunks of 64 k => KPAD 320
#define EH0     10112       // 79 tiles of 128
#define EH1     (N_EDGES - EH0)

// ---------------- scratch ----------------
__device__ __align__(128) __half g_xh[(size_t)N_NODES * 320];
__device__ __align__(128) __half g_xwE[(size_t)N_EDGES * 256];
__device__ __align__(128) __half g_h16[(size_t)N_NODES * 256];
__device__ __align__(128) __half g_h16b[(size_t)N_NODES * 256];
__device__ float g_t[N_EDGES];
__device__ float g_s[N_EDGES];
__device__ float g_c[N_NODES];
__device__ float g_cdot;
__device__ __align__(1024) __nv_bfloat16 g_Apk[(size_t)NCHUNK * N_EDGES * 64];
#define WPK_SLICE ((size_t)NCHUNK * 512 * 64)
__device__ __align__(1024) __nv_bfloat16 g_Wpk[3 * WPK_SLICE];

__device__ int   g_deg_e[N_EDGES];
__device__ int   g_deg_n[N_NODES];
__device__ float g_binv[N_EDGES];
__device__ float g_dinv[N_NODES];
__device__ int   g_off_e[N_EDGES + 1];
__device__ int   g_off_n[N_NODES + 1];
__device__ int   g_cur_e[N_EDGES];
__device__ int   g_cur_n[N_NODES];
__device__ int   g_csr_e[NNZ];
__device__ int   g_csr_n[NNZ];
__device__ int   g_bsum_e[64];
__device__ int   g_bsum_n[128];

__device__ float        g_logits[N_NODES];
__device__ unsigned int g_maxbits;
__device__ float        g_sumexp;

// ---------------- PTX helpers ----------------
__device__ __forceinline__ uint32_t smem_u32(const void* p) {
    uint32_t a;
    asm("{ .reg .u64 t; cvta.to.shared.u64 t, %1; cvt.u32.u64 %0, t; }" : "=r"(a) : "l"(p));
    return a;
}
#define MBAR_INIT(a, cnt) asm volatile("mbarrier.init.shared.b64 [%0], %1;" :: "r"(a), "r"(cnt) : "memory")
#define MBAR_EXPECT_TX(a, b) asm volatile("mbarrier.arrive.expect_tx.shared.b64 _, [%0], %1;" :: "r"(a), "r"(b) : "memory")
#define MBAR_WAIT(a, par) do {                                             \
    uint32_t _m = (a); uint32_t _p = (par); uint32_t _d;                   \
    asm volatile("{\n .reg .pred p;\n"                                     \
        " mbarrier.try_wait.parity.acquire.cta.shared::cta.b64 p, [%1], %2;\n" \
        " selp.b32 %0,1,0,p;\n}" : "=r"(_d) : "r"(_m), "r"(_p) : "memory");\
    if (!_d) {                                                             \
        asm volatile("{\n .reg .pred P1;\n"                                \
        "W_%=:\n mbarrier.try_wait.parity.acquire.cta.shared::cta.b64 P1, [%0], %1, 0x989680;\n" \
        " @P1 bra.uni D_%=;\n bra.uni W_%=;\nD_%=:\n}"                     \
        :: "r"(_m), "r"(_p) : "memory");                                   \
    } } while (0)

__device__ __forceinline__ void tma3d(uint32_t dst, const void* tmap, int x, int y, int z, uint32_t mbar) {
    asm volatile(
        "cp.async.bulk.tensor.3d.shared::cta.global.tile.mbarrier::complete_tx::bytes "
        "[%0], [%1, {%2, %3, %4}], [%5];"
        :: "r"(dst), "l"(tmap), "r"(x), "r"(y), "r"(z), "r"(mbar) : "memory");
}
__device__ __forceinline__ void ldsm4(uint32_t* r, uint32_t addr) {
    asm volatile("ldmatrix.sync.aligned.m8n8.x4.shared.b16 {%0,%1,%2,%3}, [%4];"
        : "=r"(r[0]), "=r"(r[1]), "=r"(r[2]), "=r"(r[3]) : "r"(addr));
}
__device__ __forceinline__ void mma16816(float* d, const uint32_t* a, const uint32_t* b) {
    asm volatile("mma.sync.aligned.m16n8k16.row.col.f32.bf16.bf16.f32 "
        "{%0,%1,%2,%3}, {%4,%5,%6,%7}, {%8,%9}, {%0,%1,%2,%3};"
        : "+f"(d[0]), "+f"(d[1]), "+f"(d[2]), "+f"(d[3])
        : "r"(a[0]), "r"(a[1]), "r"(a[2]), "r"(a[3]), "r"(b[0]), "r"(b[1]));
}
__device__ __forceinline__ uint32_t swz(uint32_t base, int row, int byteCol) {
    return base + row * 128 + (byteCol ^ ((row & 7) << 4));
}

// ---------------- misc helpers ----------------
__device__ __forceinline__ unsigned int enc_f(float f) {
    unsigned int u = __float_as_uint(f);
    return (u & 0x80000000u) ? ~u : (u | 0x80000000u);
}
__device__ __forceinline__ float dec_f(unsigned int u) {
    u = (u & 0x80000000u) ? (u ^ 0x80000000u) : ~u;
    return __uint_as_float(u);
}
__device__ __forceinline__ void addh8(float* a, uint4 v) {
    const __half2* h = (const __half2*)&v;
    #pragma unroll
    for (int i = 0; i < 4; i++) {
        float2 f = __half22float2(h[i]);
        a[2 * i] += f.x;
        a[2 * i + 1] += f.y;
    }
}
__device__ __forceinline__ void pack_write_hi(__nv_bfloat16* __restrict__ apk, int v, int e,
                                              float r0, float r1, float r2, float r3) {
    int chunk = v >> 4;
    int pos = (v & 15) * 4;
    size_t base = ((size_t)chunk * N_EDGES + e) * 64 + pos;
    *(__nv_bfloat162*)(apk + base)     = __halves2bfloat162(__float2bfloat16(r0), __float2bfloat16(r1));
    *(__nv_bfloat162*)(apk + base + 2) = __halves2bfloat162(__float2bfloat16(r2), __float2bfloat16(r3));
}

// ---------------- setup kernels ----------------
__global__ void k_zero_meta(int* deg_e, int* deg_n, int* cur_e, int* cur_n,
                            unsigned int* maxbits, float* sumexp, float* out) {
    int i = blockIdx.x * blockDim.x + threadIdx.x;
    int stride = gridDim.x * blockDim.x;
    for (int j = i; j < N_NODES; j += stride) {
        deg_n[j] = 0; cur_n[j] = 0;
        if (j < N_EDGES) { deg_e[j] = 0; cur_e[j] = 0; }
        if (j < 128) out[j] = 0.0f;
        if (j == 0) { *maxbits = 0u; *sumexp = 0.0f; }
    }
}

__global__ void k_count(const int* __restrict__ nidx, const int* __restrict__ eidx,
                        int* deg_n, int* deg_e) {
    int i = blockIdx.x * blockDim.x + threadIdx.x;
    if (i < NNZ) {
        atomicAdd(&deg_e[eidx[i]], 1);
        atomicAdd(&deg_n[nidx[i]], 1);
    }
}

__global__ void k_scan_local(const int* __restrict__ deg, int* __restrict__ off,
                             int* __restrict__ bsum, int n) {
    __shared__ int sh[1024];
    int i = blockIdx.x * 1024 + threadIdx.x;
    int v = (i < n) ? deg[i] : 0;
    sh[threadIdx.x] = v;
    __syncthreads();
    #pragma unroll
    for (int s = 1; s < 1024; s <<= 1) {
        int t = (threadIdx.x >= (unsigned)s) ? sh[threadIdx.x - s] : 0;
        __syncthreads();
        sh[threadIdx.x] += t;
        __syncthreads();
    }
    if (i < n) off[i] = sh[threadIdx.x] - v;
    if (threadIdx.x == 1023) bsum[blockIdx.x] = sh[1023];
}

__global__ void k_carry(int* bsum, int nb, int* tot) {
    if (threadIdx.x == 0) {
        int s = 0;
        for (int i = 0; i < nb; i++) { int v = bsum[i]; bsum[i] = s; s += v; }
        *tot = s;
    }
}

__global__ void k_scan_add(int* __restrict__ off, const int* __restrict__ bsum,
                           const int* __restrict__ deg, float* __restrict__ inv, int n) {
    int i = blockIdx.x * blockDim.x + threadIdx.x;
    if (i < n) {
        off[i] += bsum[i >> 10];
        int d = deg[i];
        inv[i] = (d > 0) ? (1.0f / (float)d) : 0.0f;
    }
}

__global__ void k_fill_e(const int* __restrict__ nidx, const int* __restrict__ eidx,
                         const int* __restrict__ off_e, int* cur_e, int* csr_e) {
    int i = blockIdx.x * blockDim.x + threadIdx.x;
    if (i < NNZ) {
        int e = eidx[i];
        int p = atomicAdd(&cur_e[e], 1);
        csr_e[off_e[e] + p] = nidx[i];
    }
}

__global__ void k_fill_n(const int* __restrict__ nidx, const int* __restrict__ eidx,
                         const int* __restrict__ off_n, int* cur_n, int* csr_n) {
    int i = blockIdx.x * blockDim.x + threadIdx.x;
    if (i < NNZ) {
        int n = nidx[i];
        int q = atomicAdd(&cur_n[n], 1);
        csr_n[off_n[n] + q] = eidx[i];
    }
}

__global__ void k_cvtX(const float* __restrict__ x, __half* __restrict__ xh) {
    int m = blockIdx.x;
    int k = threadIdx.x;   // 320
    float v = (k < 300) ? x[(size_t)m * 300 + k] : 0.0f;
    xh[(size_t)m * 320 + k] = __float2half_rn(v);
}

__global__ void k_packW(const float* __restrict__ W, int K, int N, __nv_bfloat16* __restrict__ wpk) {
    int n = blockIdx.x;
    int k = threadIdx.x;   // 320 threads
    float a = (k < K) ? W[(size_t)k * N + n] : 0.0f;
    __nv_bfloat16 h = __float2bfloat16(a);
    float r = a - __bfloat162float(h);
    int chunk = k >> 6;
    int kk = k & 63;
    wpk[((size_t)chunk * 512 + n) * 64 + kk] = h;
    wpk[((size_t)chunk * 512 + 256 + n) * 64 + kk] = __float2bfloat16(r);
}

// ---------------- edge gather (fp16 source) + fused bf16 hi pack, MLP-8 ----------------
__global__ void k_edge_pack320(const __half* __restrict__ xh,
                               const int* __restrict__ off_e, const int* __restrict__ csr_e,
                               const float* __restrict__ binv, __nv_bfloat16* __restrict__ apk,
                               int eBase, int eCount) {
    int wi = (blockIdx.x * blockDim.x + threadIdx.x) >> 5;
    if (wi >= eCount) return;
    int w = eBase + wi;
    int lane = threadIdx.x & 31;
    float a[8] = {0, 0, 0, 0, 0, 0, 0, 0};
    float b[8] = {0, 0, 0, 0, 0, 0, 0, 0};
    bool hasB = lane < 8;
    int beg = off_e[w], end = off_e[w + 1];
    int m = beg;
    for (; m + 7 < end; m += 8) {
        int idx[8];
        #pragma unroll
        for (int i = 0; i < 8; i++) idx[i] = csr_e[m + i];
        uint4 va[8];
        #pragma unroll
        for (int i = 0; i < 8; i++)
            va[i] = ((const uint4*)(xh + (size_t)idx[i] * 320))[lane];
        uint4 vb[8];
        if (hasB) {
            #pragma unroll
            for (int i = 0; i < 8; i++)
                vb[i] = ((const uint4*)(xh + (size_t)idx[i] * 320))[lane + 32];
        }
        #pragma unroll
        for (int i = 0; i < 8; i++) addh8(a, va[i]);
        if (hasB) {
            #pragma unroll
            for (int i = 0; i < 8; i++) addh8(b, vb[i]);
        }
    }
    for (; m < end; m++) {
        const uint4* r0 = (const uint4*)(xh + (size_t)csr_e[m] * 320);
        addh8(a, r0[lane]);
        if (hasB) addh8(b, r0[lane + 32]);
    }
    float bi = binv[w];
    #pragma unroll
    for (int i = 0; i < 8; i++) { a[i] *= bi; b[i] *= bi; }
    pack_write_hi(apk, 2 * lane, w, a[0], a[1], a[2], a[3]);
    pack_write_hi(apk, 2 * lane + 1, w, a[4], a[5], a[6], a[7]);
    if (hasB) {
        pack_write_hi(apk, 64 + 2 * lane, w, b[0], b[1], b[2], b[3]);
        pack_write_hi(apk, 64 + 2 * lane + 1, w, b[4], b[5], b[6], b[7]);
    }
}

__global__ void k_edge_pack256(const __half* __restrict__ h,
                               const int* __restrict__ off_e, const int* __restrict__ csr_e,
                               const float* __restrict__ binv, __nv_bfloat16* __restrict__ apk,
                               int eBase, int eCount) {
    int wi = (blockIdx.x * blockDim.x + threadIdx.x) >> 5;
    if (wi >= eCount) return;
    int w = eBase + wi;
    int lane = threadIdx.x & 31;
    float a[8] = {0, 0, 0, 0, 0, 0, 0, 0};
    int beg = off_e[w], end = off_e[w + 1];
    int m = beg;
    for (; m + 7 < end; m += 8) {
        int idx[8];
        #pragma unroll
        for (int i = 0; i < 8; i++) idx[i] = csr_e[m + i];
        uint4 v[8];
        #pragma unroll
        for (int i = 0; i < 8; i++)
            v[i] = ((const uint4*)(h + (size_t)idx[i] * 256))[lane];
        #pragma unroll
        for (int i = 0; i < 8; i++) addh8(a, v[i]);
    }
    for (; m < end; m++)
        addh8(a, ((const uint4*)(h + (size_t)csr_e[m] * 256))[lane]);
    float bi = binv[w];
    #pragma unroll
    for (int i = 0; i < 8; i++) a[i] *= bi;
    pack_write_hi(apk, 2 * lane, w, a[0], a[1], a[2], a[3]);
    pack_write_hi(apk, 2 * lane + 1, w, a[4], a[5], a[6], a[7]);
}

// ---------------- TMA + mma.sync GEMM: A bf16, W = Whi + Wlo; fp16 out ----------------
#define STAGE_B 49152
#define N_STAGE 4
#define MB_OFF  (N_STAGE * STAGE_B)
#define SMEM_GEMM (MB_OFF + 64)

__global__ __launch_bounds__(256, 1) void k_mma_gemm(
    const __grid_constant__ CUtensorMap tmA,
    const __grid_constant__ CUtensorMap tmB,
    __half* __restrict__ C, int M, int Ncols, int chunks, int mOff) {
    extern __shared__ char smem[];
    uint32_t sb = smem_u32(smem);
    int tid = threadIdx.x;
    int lane = tid & 31;
    int wid = tid >> 5;
    int wm = wid >> 2;
    int wn = wid & 3;
    int mBase = mOff + blockIdx.y * 128;
    int nBase = blockIdx.x * 128;

    if (tid == 0) {
        #pragma unroll
        for (int s = 0; s < N_STAGE; s++) MBAR_INIT(sb + MB_OFF + s * 8, 1);
    }
    __syncthreads();
    if (tid == 0) {
        #pragma unroll
        for (int s = 0; s < N_STAGE; s++) {
            if (s < chunks) {
                MBAR_EXPECT_TX(sb + MB_OFF + s * 8, STAGE_B);
                tma3d(sb + s * STAGE_B, &tmA, 0, mBase, s, sb + MB_OFF + s * 8);
                tma3d(sb + s * STAGE_B + 16384, &tmB, 0, nBase, s, sb + MB_OFF + s * 8);
                tma3d(sb + s * STAGE_B + 32768, &tmB, 0, nBase + 256, s, sb + MB_OFF + s * 8);
            }
        }
    }

    int a_row = lane & 15;
    int a_byte = (lane >> 4) << 4;
    int b_row = ((lane & 16) >> 1) + (lane & 7);
    int b_byte = (lane & 8) * 2;

    float acc[4][4][4];
    #pragma unroll
    for (int i = 0; i < 4; i++)
        #pragma unroll
        for (int j = 0; j < 4; j++)
            #pragma unroll
            for (int q = 0; q < 4; q++) acc[i][j][q] = 0.0f;

    for (int c = 0; c < chunks; c++) {
        int st = c & (N_STAGE - 1);
        MBAR_WAIT(sb + MB_OFF + st * 8, (c >> 2) & 1);
        uint32_t sA = sb + st * STAGE_B;
        uint32_t sBh = sA + 16384;
        uint32_t sBl = sA + 32768;
        #pragma unroll
        for (int ks = 0; ks < 4; ks++) {
            int kb = ks * 32;
            uint32_t ah[4][4], bh[2][4], bl[2][4];
            #pragma unroll
            for (int i = 0; i < 4; i++) {
                int r = wm * 64 + i * 16 + a_row;
                ldsm4(ah[i], swz(sA, r, kb + a_byte));
            }
            #pragma unroll
            for (int jj = 0; jj < 2; jj++) {
                int r = wn * 32 + jj * 16 + b_row;
                ldsm4(bh[jj], swz(sBh, r, kb + b_byte));
                ldsm4(bl[jj], swz(sBl, r, kb + b_byte));
            }
            #pragma unroll
            for (int i = 0; i < 4; i++)
                #pragma unroll
                for (int j = 0; j < 4; j++) {
                    const uint32_t* bH = &bh[j >> 1][(j & 1) * 2];
                    const uint32_t* bL = &bl[j >> 1][(j & 1) * 2];
                    mma16816(acc[i][j], ah[i], bH);
                    mma16816(acc[i][j], ah[i], bL);
                }
        }
        __syncthreads();
        if (tid == 0 && c + N_STAGE < chunks) {
            MBAR_EXPECT_TX(sb + MB_OFF + st * 8, STAGE_B);
            tma3d(sb + st * STAGE_B, &tmA, 0, mBase, c + N_STAGE, sb + MB_OFF + st * 8);
            tma3d(sb + st * STAGE_B + 16384, &tmB, 0, nBase, c + N_STAGE, sb + MB_OFF + st * 8);
            tma3d(sb + st * STAGE_B + 32768, &tmB, 0, nBase + 256, c + N_STAGE, sb + MB_OFF + st * 8);
        }
    }

    #pragma unroll
    for (int i = 0; i < 4; i++) {
        int r0 = mBase + wm * 64 + i * 16 + (lane >> 2);
        #pragma unroll
        for (int j = 0; j < 4; j++) {
            int cc = nBase + wn * 32 + j * 8 + (lane & 3) * 2;
            if (r0 < M)
                *(__half2*)&C[(size_t)r0 * Ncols + cc] =
                    __floats2half2_rn(acc[i][j][0], acc[i][j][1]);
            if (r0 + 8 < M)
                *(__half2*)&C[(size_t)(r0 + 8) * Ncols + cc] =
                    __floats2half2_rn(acc[i][j][2], acc[i][j][3]);
        }
    }
}

// ---------------- node gather ----------------
__global__ void k_node_agg256(const __half* __restrict__ xwE,
                              const int* __restrict__ off_n, const int* __restrict__ csr_n,
                              const float* __restrict__ dinv, const float* __restrict__ bias,
                              __half* __restrict__ dst) {
    int w = (blockIdx.x * blockDim.x + threadIdx.x) >> 5;
    if (w >= N_NODES) return;
    int lane = threadIdx.x & 31;
    float a[8] = {0, 0, 0, 0, 0, 0, 0, 0};
    int beg = off_n[w], end = off_n[w + 1];
    int m = beg;
    for (; m + 3 < end; m += 4) {
        int e0 = csr_n[m], e1 = csr_n[m + 1], e2 = csr_n[m + 2], e3 = csr_n[m + 3];
        addh8(a, ((const uint4*)(xwE + (size_t)e0 * 256))[lane]);
        addh8(a, ((const uint4*)(xwE + (size_t)e1 * 256))[lane]);
        addh8(a, ((const uint4*)(xwE + (size_t)e2 * 256))[lane]);
        addh8(a, ((const uint4*)(xwE + (size_t)e3 * 256))[lane]);
    }
    for (; m < end; m++)
        addh8(a, ((const uint4*)(xwE + (size_t)csr_n[m] * 256))[lane]);
    float di = dinv[w];
    float4 b0 = ((const float4*)bias)[2 * lane];
    float4 b1 = ((const float4*)bias)[2 * lane + 1];
    float r[8];
    r[0] = a[0] * di + b0.x; r[1] = a[1] * di + b0.y;
    r[2] = a[2] * di + b0.z; r[3] = a[3] * di + b0.w;
    r[4] = a[4] * di + b1.x; r[5] = a[5] * di + b1.y;
    r[6] = a[6] * di + b1.z; r[7] = a[7] * di + b1.w;
    #pragma unroll
    for (int i = 0; i < 8; i++) r[i] = r[i] > 0.f ? r[i] : 0.01f * r[i];
    __half2 o[4];
    #pragma unroll
    for (int i = 0; i < 4; i++) o[i] = __floats2half2_rn(r[2 * i], r[2 * i + 1]);
    ((uint4*)(dst + (size_t)w * 256))[lane] = *(const uint4*)o;
}

// ---------------- final-layer algebraic tail ----------------
__global__ void k_cdot(const float* __restrict__ b3, const float* __restrict__ aw,
                       const float* __restrict__ ab, float* __restrict__ cdot) {
    int f = threadIdx.x;   // 128
    float v = b3[f] * aw[f];
    #pragma unroll
    for (int o = 16; o; o >>= 1) v += __shfl_xor_sync(0xffffffffu, v, o);
    __shared__ float sm[4];
    if ((f & 31) == 0) sm[f >> 5] = v;
    __syncthreads();
    if (f == 0) *cdot = sm[0] + sm[1] + sm[2] + sm[3] + ab[0];
}

__global__ void k_edge_dot(const __half* __restrict__ xwE, const float* __restrict__ aw,
                           float* __restrict__ t) {
    int e = (blockIdx.x * blockDim.x + threadIdx.x) >> 5;
    if (e >= N_EDGES) return;
    int lane = threadIdx.x & 31;
    uint2 v = ((const uint2*)(xwE + (size_t)e * 128))[lane];
    const __half2* h = (const __half2*)&v;
    float2 f0 = __half22float2(h[0]);
    float2 f1 = __half22float2(h[1]);
    float4 wv = ((const float4*)aw)[lane];
    float d = f0.x * wv.x + f0.y * wv.y + f1.x * wv.z + f1.y * wv.w;
    #pragma unroll
    for (int o = 16; o; o >>= 1) d += __shfl_xor_sync(0xffffffffu, d, o);
    if (lane == 0) t[e] = d;
}

__global__ void k_logits_node(const float* __restrict__ t,
                              const int* __restrict__ off_n, const int* __restrict__ csr_n,
                              const float* __restrict__ dinv, const float* __restrict__ cdot,
                              float* __restrict__ logits, unsigned int* maxbits) {
    int n = blockIdx.x * blockDim.x + threadIdx.x;
    float lg = -3.4e38f;
    if (n < N_NODES) {
        float s = 0.f;
        int beg = off_n[n], end = off_n[n + 1];
        for (int m = beg; m < end; m++) s += t[csr_n[m]];
        lg = dinv[n] * s + *cdot;
        logits[n] = lg;
    }
    #pragma unroll
    for (int o = 16; o; o >>= 1) lg = fmaxf(lg, __shfl_xor_sync(0xffffffffu, lg, o));
    __shared__ float sm[8];
    if ((threadIdx.x & 31) == 0) sm[threadIdx.x >> 5] = lg;
    __syncthreads();
    if (threadIdx.x < 8) {
        float mv = sm[threadIdx.x];
        #pragma unroll
        for (int o = 4; o; o >>= 1) mv = fmaxf(mv, __shfl_xor_sync(0xffu, mv, o));
        if (threadIdx.x == 0) atomicMax(maxbits, enc_f(mv));
    }
}

__global__ void k_sumexp_coef(const float* __restrict__ logits,
                              const unsigned int* __restrict__ maxbits,
                              const float* __restrict__ dinv,
                              float* __restrict__ c, float* sumexp) {
    float mx = dec_f(*maxbits);
    int i = blockIdx.x * blockDim.x + threadIdx.x;
    int stride = gridDim.x * blockDim.x;
    float s = 0.f;
    for (int j = i; j < N_NODES; j += stride) {
        float ev = expf(logits[j] - mx);
        c[j] = ev * dinv[j];
        s += ev;
    }
    #pragma unroll
    for (int o = 16; o; o >>= 1) s += __shfl_xor_sync(0xffffffffu, s, o);
    __shared__ float sm[8];
    if ((threadIdx.x & 31) == 0) sm[threadIdx.x >> 5] = s;
    __syncthreads();
    if (threadIdx.x < 8) {
        float tt = sm[threadIdx.x];
        #pragma unroll
        for (int o = 4; o; o >>= 1) tt += __shfl_xor_sync(0xffu, tt, o);
        if (threadIdx.x == 0) atomicAdd(sumexp, tt);
    }
}

__global__ void k_edge_coef(const float* __restrict__ c,
                            const int* __restrict__ off_e, const int* __restrict__ csr_e,
                            float* __restrict__ s) {
    int e = (blockIdx.x * blockDim.x + threadIdx.x) >> 5;
    if (e >= N_EDGES) return;
    int lane = threadIdx.x & 31;
    float acc = 0.f;
    int beg = off_e[e], end = off_e[e + 1];
    for (int m = beg + lane; m < end; m += 32) acc += c[csr_e[m]];
    #pragma unroll
    for (int o = 16; o; o >>= 1) acc += __shfl_xor_sync(0xffffffffu, acc, o);
    if (lane == 0) s[e] = acc;
}

__global__ void k_final_sum(const __half* __restrict__ xwE, const float* __restrict__ s,
                            float* __restrict__ out) {
    int f = threadIdx.x;   // 128
    int e0 = blockIdx.x * 128;
    int e1 = min(e0 + 128, N_EDGES);
    float acc = 0.f;
    for (int e = e0; e < e1; e++)
        acc += s[e] * __half2float(xwE[(size_t)e * 128 + f]);
    atomicAdd(&out[f], acc);
}

__global__ void k_finalize(float* __restrict__ out, const float* __restrict__ sumexp,
                           const float* __restrict__ b3) {
    int f = threadIdx.x;
    out[f] = out[f] / (*sumexp) + b3[f];
}

// ---------------- host-side tensormap plumbing ----------------
typedef CUresult (*PFN_encodeTmap)(
    CUtensorMap*, CUtensorMapDataType, unsigned int, void*,
    const unsigned long long*, const unsigned long long*,
    const unsigned int*, const unsigned int*,
    CUtensorMapInterleave, CUtensorMapSwizzle, CUtensorMapL2promotion, CUtensorMapFloatOOBfill);

// ---------------- launch ----------------
extern "C" void kernel_launch(void* const* d_in, const int* in_sizes, int n_in,
                              void* d_out, int out_size) {
    const float* x   = (const float*)d_in[0];
    const int*   hei = (const int*)d_in[1];
    const int*   nidx = hei;
    const int*   eidx = hei + NNZ;
    const float* W1 = (const float*)d_in[2];
    const float* b1 = (const float*)d_in[3];
    const float* W2 = (const float*)d_in[4];
    const float* b2 = (const float*)d_in[5];
    const float* W3 = (const float*)d_in[6];
    const float* b3 = (const float*)d_in[7];
    const float* aw = (const float*)d_in[8];
    const float* ab = (const float*)d_in[9];
    float* out = (float*)d_out;

    static __half *p_xh = nullptr, *p_xwE, *p_h16, *p_h16b;
    static float *p_t, *p_s, *p_c, *p_cdot;
    static float *p_binv, *p_dinv, *p_logits, *p_sumexp;
    static int *p_deg_e, *p_deg_n, *p_off_e, *p_off_n, *p_cur_e, *p_cur_n, *p_csr_e, *p_csr_n;
    static int *p_bsum_e, *p_bsum_n;
    static unsigned int* p_maxbits;
    static __nv_bfloat16 *p_Apk, *p_Wpk;
    static CUtensorMap tmA, tmB1, tmB2, tmB3;
    static cudaStream_t s1;
    static cudaEvent_t evFork, evCnt, evPrep, evN, evA[3], evB[3];
    if (!p_xh) {
        cudaGetSymbolAddress((void**)&p_xh, g_xh);
        cudaGetSymbolAddress((void**)&p_xwE, g_xwE);
        cudaGetSymbolAddress((void**)&p_h16, g_h16);
        cudaGetSymbolAddress((void**)&p_h16b, g_h16b);
        cudaGetSymbolAddress((void**)&p_t, g_t);
        cudaGetSymbolAddress((void**)&p_s, g_s);
        cudaGetSymbolAddress((void**)&p_c, g_c);
        cudaGetSymbolAddress((void**)&p_cdot, g_cdot);
        cudaGetSymbolAddress((void**)&p_binv, g_binv);
        cudaGetSymbolAddress((void**)&p_dinv, g_dinv);
        cudaGetSymbolAddress((void**)&p_logits, g_logits);
        cudaGetSymbolAddress((void**)&p_sumexp, g_sumexp);
        cudaGetSymbolAddress((void**)&p_deg_e, g_deg_e);
        cudaGetSymbolAddress((void**)&p_deg_n, g_deg_n);
        cudaGetSymbolAddress((void**)&p_off_e, g_off_e);
        cudaGetSymbolAddress((void**)&p_off_n, g_off_n);
        cudaGetSymbolAddress((void**)&p_cur_e, g_cur_e);
        cudaGetSymbolAddress((void**)&p_cur_n, g_cur_n);
        cudaGetSymbolAddress((void**)&p_csr_e, g_csr_e);
        cudaGetSymbolAddress((void**)&p_csr_n, g_csr_n);
        cudaGetSymbolAddress((void**)&p_bsum_e, g_bsum_e);
        cudaGetSymbolAddress((void**)&p_bsum_n, g_bsum_n);
        cudaGetSymbolAddress((void**)&p_maxbits, g_maxbits);
        cudaGetSymbolAddress((void**)&p_Apk, g_Apk);
        cudaGetSymbolAddress((void**)&p_Wpk, g_Wpk);
        cudaFuncSetAttribute(k_mma_gemm, cudaFuncAttributeMaxDynamicSharedMemorySize, SMEM_GEMM);
        cudaStreamCreateWithFlags(&s1, cudaStreamNonBlocking);
        cudaEventCreateWithFlags(&evFork, cudaEventDisableTiming);
        cudaEventCreateWithFlags(&evCnt, cudaEventDisableTiming);
        cudaEventCreateWithFlags(&evPrep, cudaEventDisableTiming);
        cudaEventCreateWithFlags(&evN, cudaEventDisableTiming);
        for (int i = 0; i < 3; i++) {
            cudaEventCreateWithFlags(&evA[i], cudaEventDisableTiming);
            cudaEventCreateWithFlags(&evB[i], cudaEventDisableTiming);
        }

        void* fp = nullptr;
        cudaDriverEntryPointQueryResult qr;
        cudaGetDriverEntryPoint("cuTensorMapEncodeTiled", &fp, cudaEnableDefault, &qr);
        PFN_encodeTmap enc = (PFN_encodeTmap)fp;
        unsigned long long dimsA[3] = {128ull, (unsigned long long)N_EDGES, (unsigned long long)NCHUNK};
        unsigned long long strA[2]  = {128ull, 128ull * N_EDGES};
        unsigned long long dimsB[3] = {128ull, 512ull, (unsigned long long)NCHUNK};
        unsigned long long strB[2]  = {128ull, 128ull * 512ull};
        unsigned int box[3] = {128u, 128u, 1u};
        unsigned int est[3] = {1u, 1u, 1u};
        enc(&tmA, CU_TENSOR_MAP_DATA_TYPE_UINT8, 3, (void*)p_Apk, dimsA, strA, box, est,
            CU_TENSOR_MAP_INTERLEAVE_NONE, CU_TENSOR_MAP_SWIZZLE_128B,
            CU_TENSOR_MAP_L2_PROMOTION_L2_128B, CU_TENSOR_MAP_FLOAT_OOB_FILL_NONE);
        enc(&tmB1, CU_TENSOR_MAP_DATA_TYPE_UINT8, 3, (void*)(p_Wpk), dimsB, strB, box, est,
            CU_TENSOR_MAP_INTERLEAVE_NONE, CU_TENSOR_MAP_SWIZZLE_128B,
            CU_TENSOR_MAP_L2_PROMOTION_L2_128B, CU_TENSOR_MAP_FLOAT_OOB_FILL_NONE);
        enc(&tmB2, CU_TENSOR_MAP_DATA_TYPE_UINT8, 3, (void*)(p_Wpk + WPK_SLICE), dimsB, strB, box, est,
            CU_TENSOR_MAP_INTERLEAVE_NONE, CU_TENSOR_MAP_SWIZZLE_128B,
            CU_TENSOR_MAP_L2_PROMOTION_L2_128B, CU_TENSOR_MAP_FLOAT_OOB_FILL_NONE);
        enc(&tmB3, CU_TENSOR_MAP_DATA_TYPE_UINT8, 3, (void*)(p_Wpk + 2 * WPK_SLICE), dimsB, strB, box, est,
            CU_TENSOR_MAP_INTERLEAVE_NONE, CU_TENSOR_MAP_SWIZZLE_128B,
            CU_TENSOR_MAP_L2_PROMOTION_L2_128B, CU_TENSOR_MAP_FLOAT_OOB_FILL_NONE);
    }

    // ---- fork: conversions on s1; CSR edge-side on stream 0 ----
    cudaEventRecord(evFork, 0);
    cudaStreamWaitEvent(s1, evFork, 0);
    k_cvtX<<<N_NODES, 320, 0, s1>>>(x, p_xh);
    k_packW<<<256, 320, 0, s1>>>(W1, 300, 256, p_Wpk);
    k_packW<<<256, 320, 0, s1>>>(W2, 256, 256, p_Wpk + WPK_SLICE);
    k_packW<<<128, 320, 0, s1>>>(W3, 256, 128, p_Wpk + 2 * WPK_SLICE);
    k_cdot<<<1, 128, 0, s1>>>(b3, aw, ab, p_cdot);
    cudaEventRecord(evPrep, s1);

    k_zero_meta<<<400, 256>>>(p_deg_e, p_deg_n, p_cur_e, p_cur_n, p_maxbits, p_sumexp, out);
    k_count<<<(NNZ + 255) / 256, 256>>>(nidx, eidx, p_deg_n, p_deg_e);
    cudaEventRecord(evCnt, 0);

    const int NBE = (N_EDGES + 1023) / 1024;
    const int NBN = (N_NODES + 1023) / 1024;
    k_scan_local<<<NBE, 1024>>>(p_deg_e, p_off_e, p_bsum_e, N_EDGES);
    k_carry<<<1, 32>>>(p_bsum_e, NBE, p_off_e + N_EDGES);
    k_scan_add<<<(N_EDGES + 255) / 256, 256>>>(p_off_e, p_bsum_e, p_deg_e, p_binv, N_EDGES);
    k_fill_e<<<(NNZ + 255) / 256, 256>>>(nidx, eidx, p_off_e, p_cur_e, p_csr_e);

    cudaStreamWaitEvent(s1, evCnt, 0);
    k_scan_local<<<NBN, 1024, 0, s1>>>(p_deg_n, p_off_n, p_bsum_n, N_NODES);
    k_carry<<<1, 32, 0, s1>>>(p_bsum_n, NBN, p_off_n + N_NODES);
    k_scan_add<<<(N_NODES + 255) / 256, 256, 0, s1>>>(p_off_n, p_bsum_n, p_deg_n, p_dinv, N_NODES);
    k_fill_n<<<(NNZ + 255) / 256, 256, 0, s1>>>(nidx, eidx, p_off_n, p_cur_n, p_csr_n);
    cudaEventRecord(evN, s1);

    cudaStreamWaitEvent(0, evPrep, 0);

    const int PB0 = (EH0 * 32) / 256;          // 1264
    const int PB1 = (EH1 * 32 + 255) / 256;    // 1236
    const int GY0 = EH0 / 128;                 // 79
    const int GY1 = (EH1 + 127) / 128;         // 78
    const int NB = (N_NODES * 32) / 256;       // 12500
    const int EB = (N_EDGES * 32) / 256;       // 2500
    const int GM = (N_EDGES + 127) / 128;      // 157

    // ---- layer 1 (pipelined halves) ----
    k_edge_pack320<<<PB0, 256>>>(p_xh, p_off_e, p_csr_e, p_binv, p_Apk, 0, EH0);
    cudaEventRecord(evA[0], 0);
    k_mma_gemm<<<dim3(2, GY0), 256, SMEM_GEMM>>>(tmA, tmB1, p_xwE, N_EDGES, 256, 5, 0);
    cudaStreamWaitEvent(s1, evA[0], 0);
    k_edge_pack320<<<PB1, 256, 0, s1>>>(p_xh, p_off_e, p_csr_e, p_binv, p_Apk, EH0, EH1);
    k_mma_gemm<<<dim3(2, GY1), 256, SMEM_GEMM, s1>>>(tmA, tmB1, p_xwE, N_EDGES, 256, 5, EH0);
    cudaEventRecord(evB[0], s1);
    cudaStreamWaitEvent(0, evB[0], 0);
    cudaStreamWaitEvent(0, evN, 0);
    k_node_agg256<<<NB, 256>>>(p_xwE, p_off_n, p_csr_n, p_dinv, b1, p_h16);

    // ---- layer 2 ----
    k_edge_pack256<<<PB0, 256>>>(p_h16, p_off_e, p_csr_e, p_binv, p_Apk, 0, EH0);
    cudaEventRecord(evA[1], 0);
    k_mma_gemm<<<dim3(2, GY0), 256, SMEM_GEMM>>>(tmA, tmB2, p_xwE, N_EDGES, 256, 4, 0);
    cudaStreamWaitEvent(s1, evA[1], 0);
    k_edge_pack256<<<PB1, 256, 0, s1>>>(p_h16, p_off_e, p_csr_e, p_binv, p_Apk, EH0, EH1);
    k_mma_gemm<<<dim3(2, GY1), 256, SMEM_GEMM, s1>>>(tmA, tmB2, p_xwE, N_EDGES, 256, 4, EH0);
    cudaEventRecord(evB[1], s1);
    cudaStreamWaitEvent(0, evB[1], 0);
    k_node_agg256<<<NB, 256>>>(p_xwE, p_off_n, p_csr_n, p_dinv, b2, p_h16b);

    // ---- layer 3: pipelined edge GEMM then algebraic pooling tail ----
    k_edge_pack256<<<PB0, 256>>>(p_h16b, p_off_e, p_csr_e, p_binv, p_Apk, 0, EH0);
    cudaEventRecord(evA[2], 0);
    k_mma_gemm<<<dim3(1, GY0), 256, SMEM_GEMM>>>(tmA, tmB3, p_xwE, N_EDGES, 128, 4, 0);
    cudaStreamWaitEvent(s1, evA[2], 0);
    k_edge_pack256<<<PB1, 256, 0, s1>>>(p_h16b, p_off_e, p_csr_e, p_binv, p_Apk, EH0, EH1);
    k_mma_gemm<<<dim3(1, GY1), 256, SMEM_GEMM, s1>>>(tmA, tmB3, p_xwE, N_EDGES, 128, 4, EH0);
    cudaEventRecord(evB[2], s1);
    cudaStreamWaitEvent(0, evB[2], 0);
    k_edge_dot<<<EB, 256>>>(p_xwE, aw, p_t);
    k_logits_node<<<(N_NODES + 255) / 256, 256>>>(p_t, p_off_n, p_csr_n, p_dinv, p_cdot,
                                                  p_logits, p_maxbits);
    k_sumexp_coef<<<512, 256>>>(p_logits, p_maxbits, p_dinv, p_c, p_sumexp);
    k_edge_coef<<<EB, 256>>>(p_c, p_off_e, p_csr_e, p_s);
    k_final_sum<<<GM, 128>>>(p_xwE, p_s, out);
    k_finalize<<<1, 128>>>(out, p_sumexp, b3);
}

// round 13
// speedup vs baseline: 1.0795x; 1.0795x over previous
#include <cuda_runtime.h>
#include <cuda.h>
#include <cuda_bf16.h>
#include <cuda_fp16.h>
#include <math.h>
#include <stdint.h>

#define N_NODES 100000
#define N_EDGES 20000
#define NNZ     1600000
#define NCHUNK  5           // 5 chunks of 64 k => KPAD 320

// ---------------- scratch ----------------
__device__ __align__(128) __half g_xh[(size_t)N_NODES * 320];
__device__ __align__(128) __half g_xwE[(size_t)N_EDGES * 256];
__device__ __align__(128) __half g_h16[(size_t)N_NODES * 256];
__device__ __align__(128) __half g_h16b[(size_t)N_NODES * 256];
__device__ float g_t[N_EDGES];
__device__ float g_s[N_EDGES];
__device__ float g_c[N_NODES];
__device__ float g_cdot;
__device__ __align__(1024) __nv_bfloat16 g_Apk[(size_t)NCHUNK * N_EDGES * 64];
#define WPK_SLICE ((size_t)NCHUNK * 512 * 64)
__device__ __align__(1024) __nv_bfloat16 g_Wpk[3 * WPK_SLICE];

__device__ int   g_deg_e[N_EDGES];
__device__ int   g_deg_n[N_NODES];
__device__ float g_binv[N_EDGES];
__device__ float g_dinv[N_NODES];
__device__ int   g_off_e[N_EDGES + 1];
__device__ int   g_off_n[N_NODES + 1];
__device__ int   g_cur_e[N_EDGES];
__device__ int   g_cur_n[N_NODES];
__device__ int   g_csr_e[NNZ];
__device__ int   g_csr_n[NNZ];
__device__ int   g_bsum_e[64];
__device__ int   g_bsum_n[128];

__device__ float        g_logits[N_NODES];
__device__ unsigned int g_maxbits;
__device__ float        g_sumexp;

// ---------------- PTX helpers ----------------
__device__ __forceinline__ uint32_t smem_u32(const void* p) {
    uint32_t a;
    asm("{ .reg .u64 t; cvta.to.shared.u64 t, %1; cvt.u32.u64 %0, t; }" : "=r"(a) : "l"(p));
    return a;
}
#define MBAR_INIT(a, cnt) asm volatile("mbarrier.init.shared.b64 [%0], %1;" :: "r"(a), "r"(cnt) : "memory")
#define MBAR_EXPECT_TX(a, b) asm volatile("mbarrier.arrive.expect_tx.shared.b64 _, [%0], %1;" :: "r"(a), "r"(b) : "memory")
#define MBAR_WAIT(a, par) do {                                             \
    uint32_t _m = (a); uint32_t _p = (par); uint32_t _d;                   \
    asm volatile("{\n .reg .pred p;\n"                                     \
        " mbarrier.try_wait.parity.acquire.cta.shared::cta.b64 p, [%1], %2;\n" \
        " selp.b32 %0,1,0,p;\n}" : "=r"(_d) : "r"(_m), "r"(_p) : "memory");\
    if (!_d) {                                                             \
        asm volatile("{\n .reg .pred P1;\n"                                \
        "W_%=:\n mbarrier.try_wait.parity.acquire.cta.shared::cta.b64 P1, [%0], %1, 0x989680;\n" \
        " @P1 bra.uni D_%=;\n bra.uni W_%=;\nD_%=:\n}"                     \
        :: "r"(_m), "r"(_p) : "memory");                                   \
    } } while (0)

__device__ __forceinline__ void tma3d(uint32_t dst, const void* tmap, int x, int y, int z, uint32_t mbar) {
    asm volatile(
        "cp.async.bulk.tensor.3d.shared::cta.global.tile.mbarrier::complete_tx::bytes "
        "[%0], [%1, {%2, %3, %4}], [%5];"
        :: "r"(dst), "l"(tmap), "r"(x), "r"(y), "r"(z), "r"(mbar) : "memory");
}
__device__ __forceinline__ void ldsm4(uint32_t* r, uint32_t addr) {
    asm volatile("ldmatrix.sync.aligned.m8n8.x4.shared.b16 {%0,%1,%2,%3}, [%4];"
        : "=r"(r[0]), "=r"(r[1]), "=r"(r[2]), "=r"(r[3]) : "r"(addr));
}
__device__ __forceinline__ void mma16816(float* d, const uint32_t* a, const uint32_t* b) {
    asm volatile("mma.sync.aligned.m16n8k16.row.col.f32.bf16.bf16.f32 "
        "{%0,%1,%2,%3}, {%4,%5,%6,%7}, {%8,%9}, {%0,%1,%2,%3};"
        : "+f"(d[0]), "+f"(d[1]), "+f"(d[2]), "+f"(d[3])
        : "r"(a[0]), "r"(a[1]), "r"(a[2]), "r"(a[3]), "r"(b[0]), "r"(b[1]));
}
__device__ __forceinline__ uint32_t swz(uint32_t base, int row, int byteCol) {
    return base + row * 128 + (byteCol ^ ((row & 7) << 4));
}

// ---------------- misc helpers ----------------
__device__ __forceinline__ unsigned int enc_f(float f) {
    unsigned int u = __float_as_uint(f);
    return (u & 0x80000000u) ? ~u : (u | 0x80000000u);
}
__device__ __forceinline__ float dec_f(unsigned int u) {
    u = (u & 0x80000000u) ? (u ^ 0x80000000u) : ~u;
    return __uint_as_float(u);
}
__device__ __forceinline__ void addh8(float* a, uint4 v) {
    const __half2* h = (const __half2*)&v;
    #pragma unroll
    for (int i = 0; i < 4; i++) {
        float2 f = __half22float2(h[i]);
        a[2 * i] += f.x;
        a[2 * i + 1] += f.y;
    }
}
__device__ __forceinline__ void pack_write_hi(__nv_bfloat16* __restrict__ apk, int v, int e,
                                              float r0, float r1, float r2, float r3) {
    int chunk = v >> 4;
    int pos = (v & 15) * 4;
    size_t base = ((size_t)chunk * N_EDGES + e) * 64 + pos;
    *(__nv_bfloat162*)(apk + base)     = __halves2bfloat162(__float2bfloat16(r0), __float2bfloat16(r1));
    *(__nv_bfloat162*)(apk + base + 2) = __halves2bfloat162(__float2bfloat16(r2), __float2bfloat16(r3));
}

// ---------------- setup kernels ----------------
__global__ void k_zero_meta(int* deg_e, int* deg_n, int* cur_e, int* cur_n,
                            unsigned int* maxbits, float* sumexp, float* out) {
    int i = blockIdx.x * blockDim.x + threadIdx.x;
    int stride = gridDim.x * blockDim.x;
    for (int j = i; j < N_NODES; j += stride) {
        deg_n[j] = 0; cur_n[j] = 0;
        if (j < N_EDGES) { deg_e[j] = 0; cur_e[j] = 0; }
        if (j < 128) out[j] = 0.0f;
        if (j == 0) { *maxbits = 0u; *sumexp = 0.0f; }
    }
}

__global__ void k_count(const int* __restrict__ nidx, const int* __restrict__ eidx,
                        int* deg_n, int* deg_e) {
    int i = blockIdx.x * blockDim.x + threadIdx.x;
    if (i < NNZ) {
        atomicAdd(&deg_e[eidx[i]], 1);
        atomicAdd(&deg_n[nidx[i]], 1);
    }
}

__global__ void k_scan_local(const int* __restrict__ deg, int* __restrict__ off,
                             int* __restrict__ bsum, int n) {
    __shared__ int sh[1024];
    int i = blockIdx.x * 1024 + threadIdx.x;
    int v = (i < n) ? deg[i] : 0;
    sh[threadIdx.x] = v;
    __syncthreads();
    #pragma unroll
    for (int s = 1; s < 1024; s <<= 1) {
        int t = (threadIdx.x >= (unsigned)s) ? sh[threadIdx.x - s] : 0;
        __syncthreads();
        sh[threadIdx.x] += t;
        __syncthreads();
    }
    if (i < n) off[i] = sh[threadIdx.x] - v;
    if (threadIdx.x == 1023) bsum[blockIdx.x] = sh[1023];
}

__global__ void k_carry(int* bsum, int nb, int* tot) {
    if (threadIdx.x == 0) {
        int s = 0;
        for (int i = 0; i < nb; i++) { int v = bsum[i]; bsum[i] = s; s += v; }
        *tot = s;
    }
}

__global__ void k_scan_add(int* __restrict__ off, const int* __restrict__ bsum,
                           const int* __restrict__ deg, float* __restrict__ inv, int n) {
    int i = blockIdx.x * blockDim.x + threadIdx.x;
    if (i < n) {
        off[i] += bsum[i >> 10];
        int d = deg[i];
        inv[i] = (d > 0) ? (1.0f / (float)d) : 0.0f;
    }
}

__global__ void k_fill_e(const int* __restrict__ nidx, const int* __restrict__ eidx,
                         const int* __restrict__ off_e, int* cur_e, int* csr_e) {
    int i = blockIdx.x * blockDim.x + threadIdx.x;
    if (i < NNZ) {
        int e = eidx[i];
        int p = atomicAdd(&cur_e[e], 1);
        csr_e[off_e[e] + p] = nidx[i];
    }
}

__global__ void k_fill_n(const int* __restrict__ nidx, const int* __restrict__ eidx,
                         const int* __restrict__ off_n, int* cur_n, int* csr_n) {
    int i = blockIdx.x * blockDim.x + threadIdx.x;
    if (i < NNZ) {
        int n = nidx[i];
        int q = atomicAdd(&cur_n[n], 1);
        csr_n[off_n[n] + q] = eidx[i];
    }
}

__global__ void k_cvtX(const float* __restrict__ x, __half* __restrict__ xh) {
    int m = blockIdx.x;
    int k = threadIdx.x;   // 320
    float v = (k < 300) ? x[(size_t)m * 300 + k] : 0.0f;
    xh[(size_t)m * 320 + k] = __float2half_rn(v);
}

__global__ void k_packW(const float* __restrict__ W, int K, int N, __nv_bfloat16* __restrict__ wpk) {
    int n = blockIdx.x;
    int k = threadIdx.x;   // 320 threads
    float a = (k < K) ? W[(size_t)k * N + n] : 0.0f;
    __nv_bfloat16 h = __float2bfloat16(a);
    float r = a - __bfloat162float(h);
    int chunk = k >> 6;
    int kk = k & 63;
    wpk[((size_t)chunk * 512 + n) * 64 + kk] = h;
    wpk[((size_t)chunk * 512 + 256 + n) * 64 + kk] = __float2bfloat16(r);
}

// ---------------- edge gather (fp16 source) + fused bf16 hi pack, MLP-8 ----------------
__global__ void k_edge_pack320(const __half* __restrict__ xh,
                               const int* __restrict__ off_e, const int* __restrict__ csr_e,
                               const float* __restrict__ binv, __nv_bfloat16* __restrict__ apk) {
    int w = (blockIdx.x * blockDim.x + threadIdx.x) >> 5;
    if (w >= N_EDGES) return;
    int lane = threadIdx.x & 31;
    float a[8] = {0, 0, 0, 0, 0, 0, 0, 0};
    float b[8] = {0, 0, 0, 0, 0, 0, 0, 0};
    bool hasB = lane < 8;
    int beg = off_e[w], end = off_e[w + 1];
    int m = beg;
    for (; m + 7 < end; m += 8) {
        int idx[8];
        #pragma unroll
        for (int i = 0; i < 8; i++) idx[i] = csr_e[m + i];
        uint4 va[8];
        #pragma unroll
        for (int i = 0; i < 8; i++)
            va[i] = ((const uint4*)(xh + (size_t)idx[i] * 320))[lane];
        uint4 vb[8];
        if (hasB) {
            #pragma unroll
            for (int i = 0; i < 8; i++)
                vb[i] = ((const uint4*)(xh + (size_t)idx[i] * 320))[lane + 32];
        }
        #pragma unroll
        for (int i = 0; i < 8; i++) addh8(a, va[i]);
        if (hasB) {
            #pragma unroll
            for (int i = 0; i < 8; i++) addh8(b, vb[i]);
        }
    }
    for (; m < end; m++) {
        const uint4* r0 = (const uint4*)(xh + (size_t)csr_e[m] * 320);
        addh8(a, r0[lane]);
        if (hasB) addh8(b, r0[lane + 32]);
    }
    float bi = binv[w];
    #pragma unroll
    for (int i = 0; i < 8; i++) { a[i] *= bi; b[i] *= bi; }
    pack_write_hi(apk, 2 * lane, w, a[0], a[1], a[2], a[3]);
    pack_write_hi(apk, 2 * lane + 1, w, a[4], a[5], a[6], a[7]);
    if (hasB) {
        pack_write_hi(apk, 64 + 2 * lane, w, b[0], b[1], b[2], b[3]);
        pack_write_hi(apk, 64 + 2 * lane + 1, w, b[4], b[5], b[6], b[7]);
    }
}

__global__ void k_edge_pack256(const __half* __restrict__ h,
                               const int* __restrict__ off_e, const int* __restrict__ csr_e,
                               const float* __restrict__ binv, __nv_bfloat16* __restrict__ apk) {
    int w = (blockIdx.x * blockDim.x + threadIdx.x) >> 5;
    if (w >= N_EDGES) return;
    int lane = threadIdx.x & 31;
    float a[8] = {0, 0, 0, 0, 0, 0, 0, 0};
    int beg = off_e[w], end = off_e[w + 1];
    int m = beg;
    for (; m + 7 < end; m += 8) {
        int idx[8];
        #pragma unroll
        for (int i = 0; i < 8; i++) idx[i] = csr_e[m + i];
        uint4 v[8];
        #pragma unroll
        for (int i = 0; i < 8; i++)
            v[i] = ((const uint4*)(h + (size_t)idx[i] * 256))[lane];
        #pragma unroll
        for (int i = 0; i < 8; i++) addh8(a, v[i]);
    }
    for (; m < end; m++)
        addh8(a, ((const uint4*)(h + (size_t)csr_e[m] * 256))[lane]);
    float bi = binv[w];
    #pragma unroll
    for (int i = 0; i < 8; i++) a[i] *= bi;
    pack_write_hi(apk, 2 * lane, w, a[0], a[1], a[2], a[3]);
    pack_write_hi(apk, 2 * lane + 1, w, a[4], a[5], a[6], a[7]);
}

// ---------------- TMA + mma.sync GEMM: A bf16, W = Whi + Wlo; fp16 out ----------------
#define STAGE_B 49152
#define N_STAGE 4
#define MB_OFF  (N_STAGE * STAGE_B)
#define SMEM_GEMM (MB_OFF + 64)

__global__ __launch_bounds__(256, 1) void k_mma_gemm(
    const __grid_constant__ CUtensorMap tmA,
    const __grid_constant__ CUtensorMap tmB,
    __half* __restrict__ C, int M, int Ncols, int chunks) {
    extern __shared__ char smem[];
    uint32_t sb = smem_u32(smem);
    int tid = threadIdx.x;
    int lane = tid & 31;
    int wid = tid >> 5;
    int wm = wid >> 2;
    int wn = wid & 3;
    int mBase = blockIdx.y * 128;
    int nBase = blockIdx.x * 128;

    if (tid == 0) {
        #pragma unroll
        for (int s = 0; s < N_STAGE; s++) MBAR_INIT(sb + MB_OFF + s * 8, 1);
    }
    __syncthreads();
    if (tid == 0) {
        #pragma unroll
        for (int s = 0; s < N_STAGE; s++) {
            if (s < chunks) {
                MBAR_EXPECT_TX(sb + MB_OFF + s * 8, STAGE_B);
                tma3d(sb + s * STAGE_B, &tmA, 0, mBase, s, sb + MB_OFF + s * 8);
                tma3d(sb + s * STAGE_B + 16384, &tmB, 0, nBase, s, sb + MB_OFF + s * 8);
                tma3d(sb + s * STAGE_B + 32768, &tmB, 0, nBase + 256, s, sb + MB_OFF + s * 8);
            }
        }
    }

    int a_row = lane & 15;
    int a_byte = (lane >> 4) << 4;
    int b_row = ((lane & 16) >> 1) + (lane & 7);
    int b_byte = (lane & 8) * 2;

    float acc[4][4][4];
    #pragma unroll
    for (int i = 0; i < 4; i++)
        #pragma unroll
        for (int j = 0; j < 4; j++)
            #pragma unroll
            for (int q = 0; q < 4; q++) acc[i][j][q] = 0.0f;

    for (int c = 0; c < chunks; c++) {
        int st = c & (N_STAGE - 1);
        MBAR_WAIT(sb + MB_OFF + st * 8, (c >> 2) & 1);
        uint32_t sA = sb + st * STAGE_B;
        uint32_t sBh = sA + 16384;
        uint32_t sBl = sA + 32768;
        #pragma unroll
        for (int ks = 0; ks < 4; ks++) {
            int kb = ks * 32;
            uint32_t ah[4][4], bh[2][4], bl[2][4];
            #pragma unroll
            for (int i = 0; i < 4; i++) {
                int r = wm * 64 + i * 16 + a_row;
                ldsm4(ah[i], swz(sA, r, kb + a_byte));
            }
            #pragma unroll
            for (int jj = 0; jj < 2; jj++) {
                int r = wn * 32 + jj * 16 + b_row;
                ldsm4(bh[jj], swz(sBh, r, kb + b_byte));
                ldsm4(bl[jj], swz(sBl, r, kb + b_byte));
            }
            #pragma unroll
            for (int i = 0; i < 4; i++)
                #pragma unroll
                for (int j = 0; j < 4; j++) {
                    const uint32_t* bH = &bh[j >> 1][(j & 1) * 2];
                    const uint32_t* bL = &bl[j >> 1][(j & 1) * 2];
                    mma16816(acc[i][j], ah[i], bH);
                    mma16816(acc[i][j], ah[i], bL);
                }
        }
        __syncthreads();
        if (tid == 0 && c + N_STAGE < chunks) {
            MBAR_EXPECT_TX(sb + MB_OFF + st * 8, STAGE_B);
            tma3d(sb + st * STAGE_B, &tmA, 0, mBase, c + N_STAGE, sb + MB_OFF + st * 8);
            tma3d(sb + st * STAGE_B + 16384, &tmB, 0, nBase, c + N_STAGE, sb + MB_OFF + st * 8);
            tma3d(sb + st * STAGE_B + 32768, &tmB, 0, nBase + 256, c + N_STAGE, sb + MB_OFF + st * 8);
        }
    }

    #pragma unroll
    for (int i = 0; i < 4; i++) {
        int r0 = mBase + wm * 64 + i * 16 + (lane >> 2);
        #pragma unroll
        for (int j = 0; j < 4; j++) {
            int cc = nBase + wn * 32 + j * 8 + (lane & 3) * 2;
            if (r0 < M)
                *(__half2*)&C[(size_t)r0 * Ncols + cc] =
                    __floats2half2_rn(acc[i][j][0], acc[i][j][1]);
            if (r0 + 8 < M)
                *(__half2*)&C[(size_t)(r0 + 8) * Ncols + cc] =
                    __floats2half2_rn(acc[i][j][2], acc[i][j][3]);
        }
    }
}

// ---------------- node gather ----------------
__global__ void k_node_agg256(const __half* __restrict__ xwE,
                              const int* __restrict__ off_n, const int* __restrict__ csr_n,
                              const float* __restrict__ dinv, const float* __restrict__ bias,
                              __half* __restrict__ dst) {
    int w = (blockIdx.x * blockDim.x + threadIdx.x) >> 5;
    if (w >= N_NODES) return;
    int lane = threadIdx.x & 31;
    float a[8] = {0, 0, 0, 0, 0, 0, 0, 0};
    int beg = off_n[w], end = off_n[w + 1];
    int m = beg;
    for (; m + 3 < end; m += 4) {
        int e0 = csr_n[m], e1 = csr_n[m + 1], e2 = csr_n[m + 2], e3 = csr_n[m + 3];
        addh8(a, ((const uint4*)(xwE + (size_t)e0 * 256))[lane]);
        addh8(a, ((const uint4*)(xwE + (size_t)e1 * 256))[lane]);
        addh8(a, ((const uint4*)(xwE + (size_t)e2 * 256))[lane]);
        addh8(a, ((const uint4*)(xwE + (size_t)e3 * 256))[lane]);
    }
    for (; m < end; m++)
        addh8(a, ((const uint4*)(xwE + (size_t)csr_n[m] * 256))[lane]);
    float di = dinv[w];
    float4 b0 = ((const float4*)bias)[2 * lane];
    float4 b1 = ((const float4*)bias)[2 * lane + 1];
    float r[8];
    r[0] = a[0] * di + b0.x; r[1] = a[1] * di + b0.y;
    r[2] = a[2] * di + b0.z; r[3] = a[3] * di + b0.w;
    r[4] = a[4] * di + b1.x; r[5] = a[5] * di + b1.y;
    r[6] = a[6] * di + b1.z; r[7] = a[7] * di + b1.w;
    #pragma unroll
    for (int i = 0; i < 8; i++) r[i] = r[i] > 0.f ? r[i] : 0.01f * r[i];
    __half2 o[4];
    #pragma unroll
    for (int i = 0; i < 4; i++) o[i] = __floats2half2_rn(r[2 * i], r[2 * i + 1]);
    ((uint4*)(dst + (size_t)w * 256))[lane] = *(const uint4*)o;
}

// ---------------- final-layer algebraic tail ----------------
__global__ void k_cdot(const float* __restrict__ b3, const float* __restrict__ aw,
                       const float* __restrict__ ab, float* __restrict__ cdot) {
    int f = threadIdx.x;   // 128
    float v = b3[f] * aw[f];
    #pragma unroll
    for (int o = 16; o; o >>= 1) v += __shfl_xor_sync(0xffffffffu, v, o);
    __shared__ float sm[4];
    if ((f & 31) == 0) sm[f >> 5] = v;
    __syncthreads();
    if (f == 0) *cdot = sm[0] + sm[1] + sm[2] + sm[3] + ab[0];
}

__global__ void k_edge_dot(const __half* __restrict__ xwE, const float* __restrict__ aw,
                           float* __restrict__ t) {
    int e = (blockIdx.x * blockDim.x + threadIdx.x) >> 5;
    if (e >= N_EDGES) return;
    int lane = threadIdx.x & 31;
    uint2 v = ((const uint2*)(xwE + (size_t)e * 128))[lane];
    const __half2* h = (const __half2*)&v;
    float2 f0 = __half22float2(h[0]);
    float2 f1 = __half22float2(h[1]);
    float4 wv = ((const float4*)aw)[lane];
    float d = f0.x * wv.x + f0.y * wv.y + f1.x * wv.z + f1.y * wv.w;
    #pragma unroll
    for (int o = 16; o; o >>= 1) d += __shfl_xor_sync(0xffffffffu, d, o);
    if (lane == 0) t[e] = d;
}

__global__ void k_logits_node(const float* __restrict__ t,
                              const int* __restrict__ off_n, const int* __restrict__ csr_n,
                              const float* __restrict__ dinv, const float* __restrict__ cdot,
                              float* __restrict__ logits, unsigned int* maxbits) {
    int n = blockIdx.x * blockDim.x + threadIdx.x;
    float lg = -3.4e38f;
    if (n < N_NODES) {
        float s = 0.f;
        int beg = off_n[n], end = off_n[n + 1];
        for (int m = beg; m < end; m++) s += t[csr_n[m]];
        lg = dinv[n] * s + *cdot;
        logits[n] = lg;
    }
    #pragma unroll
    for (int o = 16; o; o >>= 1) lg = fmaxf(lg, __shfl_xor_sync(0xffffffffu, lg, o));
    __shared__ float sm[8];
    if ((threadIdx.x & 31) == 0) sm[threadIdx.x >> 5] = lg;
    __syncthreads();
    if (threadIdx.x < 8) {
        float mv = sm[threadIdx.x];
        #pragma unroll
        for (int o = 4; o; o >>= 1) mv = fmaxf(mv, __shfl_xor_sync(0xffu, mv, o));
        if (threadIdx.x == 0) atomicMax(maxbits, enc_f(mv));
    }
}

__global__ void k_sumexp_coef(const float* __restrict__ logits,
                              const unsigned int* __restrict__ maxbits,
                              const float* __restrict__ dinv,
                              float* __restrict__ c, float* sumexp) {
    float mx = dec_f(*maxbits);
    int i = blockIdx.x * blockDim.x + threadIdx.x;
    int stride = gridDim.x * blockDim.x;
    float s = 0.f;
    for (int j = i; j < N_NODES; j += stride) {
        float ev = expf(logits[j] - mx);
        c[j] = ev * dinv[j];
        s += ev;
    }
    #pragma unroll
    for (int o = 16; o; o >>= 1) s += __shfl_xor_sync(0xffffffffu, s, o);
    __shared__ float sm[8];
    if ((threadIdx.x & 31) == 0) sm[threadIdx.x >> 5] = s;
    __syncthreads();
    if (threadIdx.x < 8) {
        float tt = sm[threadIdx.x];
        #pragma unroll
        for (int o = 4; o; o >>= 1) tt += __shfl_xor_sync(0xffu, tt, o);
        if (threadIdx.x == 0) atomicAdd(sumexp, tt);
    }
}

__global__ void k_edge_coef(const float* __restrict__ c,
                            const int* __restrict__ off_e, const int* __restrict__ csr_e,
                            float* __restrict__ s) {
    int e = (blockIdx.x * blockDim.x + threadIdx.x) >> 5;
    if (e >= N_EDGES) return;
    int lane = threadIdx.x & 31;
    float acc = 0.f;
    int beg = off_e[e], end = off_e[e + 1];
    for (int m = beg + lane; m < end; m += 32) acc += c[csr_e[m]];
    #pragma unroll
    for (int o = 16; o; o >>= 1) acc += __shfl_xor_sync(0xffffffffu, acc, o);
    if (lane == 0) s[e] = acc;
}

__global__ void k_final_sum(const __half* __restrict__ xwE, const float* __restrict__ s,
                            float* __restrict__ out) {
    int f = threadIdx.x;   // 128
    int e0 = blockIdx.x * 128;
    int e1 = min(e0 + 128, N_EDGES);
    float acc = 0.f;
    for (int e = e0; e < e1; e++)
        acc += s[e] * __half2float(xwE[(size_t)e * 128 + f]);
    atomicAdd(&out[f], acc);
}

__global__ void k_finalize(float* __restrict__ out, const float* __restrict__ sumexp,
                           const float* __restrict__ b3) {
    int f = threadIdx.x;
    out[f] = out[f] / (*sumexp) + b3[f];
}

// ---------------- host-side tensormap plumbing ----------------
typedef CUresult (*PFN_encodeTmap)(
    CUtensorMap*, CUtensorMapDataType, unsigned int, void*,
    const unsigned long long*, const unsigned long long*,
    const unsigned int*, const unsigned int*,
    CUtensorMapInterleave, CUtensorMapSwizzle, CUtensorMapL2promotion, CUtensorMapFloatOOBfill);

// ---------------- launch ----------------
extern "C" void kernel_launch(void* const* d_in, const int* in_sizes, int n_in,
                              void* d_out, int out_size) {
    const float* x   = (const float*)d_in[0];
    const int*   hei = (const int*)d_in[1];
    const int*   nidx = hei;
    const int*   eidx = hei + NNZ;
    const float* W1 = (const float*)d_in[2];
    const float* b1 = (const float*)d_in[3];
    const float* W2 = (const float*)d_in[4];
    const float* b2 = (const float*)d_in[5];
    const float* W3 = (const float*)d_in[6];
    const float* b3 = (const float*)d_in[7];
    const float* aw = (const float*)d_in[8];
    const float* ab = (const float*)d_in[9];
    float* out = (float*)d_out;

    static __half *p_xh = nullptr, *p_xwE, *p_h16, *p_h16b;
    static float *p_t, *p_s, *p_c, *p_cdot;
    static float *p_binv, *p_dinv, *p_logits, *p_sumexp;
    static int *p_deg_e, *p_deg_n, *p_off_e, *p_off_n, *p_cur_e, *p_cur_n, *p_csr_e, *p_csr_n;
    static int *p_bsum_e, *p_bsum_n;
    static unsigned int* p_maxbits;
    static __nv_bfloat16 *p_Apk, *p_Wpk;
    static CUtensorMap tmA, tmB1, tmB2, tmB3;
    static cudaStream_t s1;
    static cudaEvent_t evFork, evCnt, evPrep, evN;
    if (!p_xh) {
        cudaGetSymbolAddress((void**)&p_xh, g_xh);
        cudaGetSymbolAddress((void**)&p_xwE, g_xwE);
        cudaGetSymbolAddress((void**)&p_h16, g_h16);
        cudaGetSymbolAddress((void**)&p_h16b, g_h16b);
        cudaGetSymbolAddress((void**)&p_t, g_t);
        cudaGetSymbolAddress((void**)&p_s, g_s);
        cudaGetSymbolAddress((void**)&p_c, g_c);
        cudaGetSymbolAddress((void**)&p_cdot, g_cdot);
        cudaGetSymbolAddress((void**)&p_binv, g_binv);
        cudaGetSymbolAddress((void**)&p_dinv, g_dinv);
        cudaGetSymbolAddress((void**)&p_logits, g_logits);
        cudaGetSymbolAddress((void**)&p_sumexp, g_sumexp);
        cudaGetSymbolAddress((void**)&p_deg_e, g_deg_e);
        cudaGetSymbolAddress((void**)&p_deg_n, g_deg_n);
        cudaGetSymbolAddress((void**)&p_off_e, g_off_e);
        cudaGetSymbolAddress((void**)&p_off_n, g_off_n);
        cudaGetSymbolAddress((void**)&p_cur_e, g_cur_e);
        cudaGetSymbolAddress((void**)&p_cur_n, g_cur_n);
        cudaGetSymbolAddress((void**)&p_csr_e, g_csr_e);
        cudaGetSymbolAddress((void**)&p_csr_n, g_csr_n);
        cudaGetSymbolAddress((void**)&p_bsum_e, g_bsum_e);
        cudaGetSymbolAddress((void**)&p_bsum_n, g_bsum_n);
        cudaGetSymbolAddress((void**)&p_maxbits, g_maxbits);
        cudaGetSymbolAddress((void**)&p_Apk, g_Apk);
        cudaGetSymbolAddress((void**)&p_Wpk, g_Wpk);
        cudaFuncSetAttribute(k_mma_gemm, cudaFuncAttributeMaxDynamicSharedMemorySize, SMEM_GEMM);
        cudaStreamCreateWithFlags(&s1, cudaStreamNonBlocking);
        cudaEventCreateWithFlags(&evFork, cudaEventDisableTiming);
        cudaEventCreateWithFlags(&evCnt, cudaEventDisableTiming);
        cudaEventCreateWithFlags(&evPrep, cudaEventDisableTiming);
        cudaEventCreateWithFlags(&evN, cudaEventDisableTiming);

        void* fp = nullptr;
        cudaDriverEntryPointQueryResult qr;
        cudaGetDriverEntryPoint("cuTensorMapEncodeTiled", &fp, cudaEnableDefault, &qr);
        PFN_encodeTmap enc = (PFN_encodeTmap)fp;
        unsigned long long dimsA[3] = {128ull, (unsigned long long)N_EDGES, (unsigned long long)NCHUNK};
        unsigned long long strA[2]  = {128ull, 128ull * N_EDGES};
        unsigned long long dimsB[3] = {128ull, 512ull, (unsigned long long)NCHUNK};
        unsigned long long strB[2]  = {128ull, 128ull * 512ull};
        unsigned int box[3] = {128u, 128u, 1u};
        unsigned int est[3] = {1u, 1u, 1u};
        enc(&tmA, CU_TENSOR_MAP_DATA_TYPE_UINT8, 3, (void*)p_Apk, dimsA, strA, box, est,
            CU_TENSOR_MAP_INTERLEAVE_NONE, CU_TENSOR_MAP_SWIZZLE_128B,
            CU_TENSOR_MAP_L2_PROMOTION_L2_128B, CU_TENSOR_MAP_FLOAT_OOB_FILL_NONE);
        enc(&tmB1, CU_TENSOR_MAP_DATA_TYPE_UINT8, 3, (void*)(p_Wpk), dimsB, strB, box, est,
            CU_TENSOR_MAP_INTERLEAVE_NONE, CU_TENSOR_MAP_SWIZZLE_128B,
            CU_TENSOR_MAP_L2_PROMOTION_L2_128B, CU_TENSOR_MAP_FLOAT_OOB_FILL_NONE);
        enc(&tmB2, CU_TENSOR_MAP_DATA_TYPE_UINT8, 3, (void*)(p_Wpk + WPK_SLICE), dimsB, strB, box, est,
            CU_TENSOR_MAP_INTERLEAVE_NONE, CU_TENSOR_MAP_SWIZZLE_128B,
            CU_TENSOR_MAP_L2_PROMOTION_L2_128B, CU_TENSOR_MAP_FLOAT_OOB_FILL_NONE);
        enc(&tmB3, CU_TENSOR_MAP_DATA_TYPE_UINT8, 3, (void*)(p_Wpk + 2 * WPK_SLICE), dimsB, strB, box, est,
            CU_TENSOR_MAP_INTERLEAVE_NONE, CU_TENSOR_MAP_SWIZZLE_128B,
            CU_TENSOR_MAP_L2_PROMOTION_L2_128B, CU_TENSOR_MAP_FLOAT_OOB_FILL_NONE);
    }

    // ---- fork: conversions on s1; CSR edge-side on stream 0 ----
    cudaEventRecord(evFork, 0);
    cudaStreamWaitEvent(s1, evFork, 0);
    k_cvtX<<<N_NODES, 320, 0, s1>>>(x, p_xh);
    k_packW<<<256, 320, 0, s1>>>(W1, 300, 256, p_Wpk);
    k_packW<<<256, 320, 0, s1>>>(W2, 256, 256, p_Wpk + WPK_SLICE);
    k_packW<<<128, 320, 0, s1>>>(W3, 256, 128, p_Wpk + 2 * WPK_SLICE);
    k_cdot<<<1, 128, 0, s1>>>(b3, aw, ab, p_cdot);
    cudaEventRecord(evPrep, s1);

    k_zero_meta<<<400, 256>>>(p_deg_e, p_deg_n, p_cur_e, p_cur_n, p_maxbits, p_sumexp, out);
    k_count<<<(NNZ + 255) / 256, 256>>>(nidx, eidx, p_deg_n, p_deg_e);
    cudaEventRecord(evCnt, 0);

    const int NBE = (N_EDGES + 1023) / 1024;
    const int NBN = (N_NODES + 1023) / 1024;
    k_scan_local<<<NBE, 1024>>>(p_deg_e, p_off_e, p_bsum_e, N_EDGES);
    k_carry<<<1, 32>>>(p_bsum_e, NBE, p_off_e + N_EDGES);
    k_scan_add<<<(N_EDGES + 255) / 256, 256>>>(p_off_e, p_bsum_e, p_deg_e, p_binv, N_EDGES);
    k_fill_e<<<(NNZ + 255) / 256, 256>>>(nidx, eidx, p_off_e, p_cur_e, p_csr_e);

    cudaStreamWaitEvent(s1, evCnt, 0);
    k_scan_local<<<NBN, 1024, 0, s1>>>(p_deg_n, p_off_n, p_bsum_n, N_NODES);
    k_carry<<<1, 32, 0, s1>>>(p_bsum_n, NBN, p_off_n + N_NODES);
    k_scan_add<<<(N_NODES + 255) / 256, 256, 0, s1>>>(p_off_n, p_bsum_n, p_deg_n, p_dinv, N_NODES);
    k_fill_n<<<(NNZ + 255) / 256, 256, 0, s1>>>(nidx, eidx, p_off_n, p_cur_n, p_csr_n);
    cudaEventRecord(evN, s1);

    cudaStreamWaitEvent(0, evPrep, 0);

    const int EB = (N_EDGES * 32) / 256;    // 2500
    const int NB = (N_NODES * 32) / 256;    // 12500
    const int GM = (N_EDGES + 127) / 128;   // 157

    // ---- layer 1 ----
    k_edge_pack320<<<EB, 256>>>(p_xh, p_off_e, p_csr_e, p_binv, p_Apk);
    k_mma_gemm<<<dim3(2, GM), 256, SMEM_GEMM>>>(tmA, tmB1, p_xwE, N_EDGES, 256, 5);
    cudaStreamWaitEvent(0, evN, 0);
    k_node_agg256<<<NB, 256>>>(p_xwE, p_off_n, p_csr_n, p_dinv, b1, p_h16);

    // ---- layer 2 ----
    k_edge_pack256<<<EB, 256>>>(p_h16, p_off_e, p_csr_e, p_binv, p_Apk);
    k_mma_gemm<<<dim3(2, GM), 256, SMEM_GEMM>>>(tmA, tmB2, p_xwE, N_EDGES, 256, 4);
    k_node_agg256<<<NB, 256>>>(p_xwE, p_off_n, p_csr_n, p_dinv, b2, p_h16b);

    // ---- layer 3: edge GEMM then algebraic pooling tail ----
    k_edge_pack256<<<EB, 256>>>(p_h16b, p_off_e, p_csr_e, p_binv, p_Apk);
    k_mma_gemm<<<dim3(1, GM), 256, SMEM_GEMM>>>(tmA, tmB3, p_xwE, N_EDGES, 128, 4);
    k_edge_dot<<<EB, 256>>>(p_xwE, aw, p_t);
    k_logits_node<<<(N_NODES + 255) / 256, 256>>>(p_t, p_off_n, p_csr_n, p_dinv, p_cdot,
                                                  p_logits, p_maxbits);
    k_sumexp_coef<<<512, 256>>>(p_logits, p_maxbits, p_dinv, p_c, p_sumexp);
    k_edge_coef<<<EB, 256>>>(p_c, p_off_e, p_csr_e, p_s);
    k_final_sum<<<GM, 128>>>(p_xwE, p_s, out);
    k_finalize<<<1, 128>>>(out, p_sumexp, b3);
}

// round 15
// speedup vs baseline: 1.0798x; 1.0003x over previous
#include <cuda_runtime.h>
#include <cuda.h>
#include <cuda_bf16.h>
#include <cuda_fp16.h>
#include <math.h>
#include <stdint.h>

#define N_NODES 100000
#define N_EDGES 20000
#define NNZ     1600000
#define NCHUNK  5           // 5 chunks of 64 k => KPAD 320

// ---------------- scratch ----------------
__device__ __align__(128) __half g_xh[(size_t)N_NODES * 320];
__device__ __align__(128) __half g_xwE[(size_t)N_EDGES * 256];
__device__ __align__(128) __half g_h16[(size_t)N_NODES * 256];
__device__ __align__(128) __half g_h16b[(size_t)N_NODES * 256];
__device__ float g_t[N_EDGES];
__device__ float g_s[N_EDGES];
__device__ float g_c[N_NODES];
__device__ float g_cdot;
__device__ __align__(1024) __nv_bfloat16 g_Apk[(size_t)NCHUNK * N_EDGES * 64];
#define WPK_SLICE ((size_t)NCHUNK * 512 * 64)
__device__ __align__(1024) __nv_bfloat16 g_Wpk[3 * WPK_SLICE];

__device__ int   g_deg_e[N_EDGES];
__device__ int   g_deg_n[N_NODES];
__device__ float g_binv[N_EDGES];
__device__ float g_dinv[N_NODES];
__device__ int   g_off_e[N_EDGES + 1];
__device__ int   g_off_n[N_NODES + 1];
__device__ int   g_cur_e[N_EDGES];
__device__ int   g_cur_n[N_NODES];
__device__ int   g_csr_e[NNZ];
__device__ int   g_csr_n[NNZ];
__device__ int   g_bsum_e[64];
__device__ int   g_bsum_n[128];

__device__ float        g_logits[N_NODES];
__device__ unsigned int g_maxbits;
__device__ float        g_sumexp;

// ---------------- PTX helpers ----------------
__device__ __forceinline__ uint32_t smem_u32(const void* p) {
    uint32_t a;
    asm("{ .reg .u64 t; cvta.to.shared.u64 t, %1; cvt.u32.u64 %0, t; }" : "=r"(a) : "l"(p));
    return a;
}
#define MBAR_INIT(a, cnt) asm volatile("mbarrier.init.shared.b64 [%0], %1;" :: "r"(a), "r"(cnt) : "memory")
#define MBAR_EXPECT_TX(a, b) asm volatile("mbarrier.arrive.expect_tx.shared.b64 _, [%0], %1;" :: "r"(a), "r"(b) : "memory")
#define MBAR_WAIT(a, par) do {                                             \
    uint32_t _m = (a); uint32_t _p = (par); uint32_t _d;                   \
    asm volatile("{\n .reg .pred p;\n"                                     \
        " mbarrier.try_wait.parity.acquire.cta.shared::cta.b64 p, [%1], %2;\n" \
        " selp.b32 %0,1,0,p;\n}" : "=r"(_d) : "r"(_m), "r"(_p) : "memory");\
    if (!_d) {                                                             \
        asm volatile("{\n .reg .pred P1;\n"                                \
        "W_%=:\n mbarrier.try_wait.parity.acquire.cta.shared::cta.b64 P1, [%0], %1, 0x989680;\n" \
        " @P1 bra.uni D_%=;\n bra.uni W_%=;\nD_%=:\n}"                     \
        :: "r"(_m), "r"(_p) : "memory");                                   \
    } } while (0)

__device__ __forceinline__ void tma3d(uint32_t dst, const void* tmap, int x, int y, int z, uint32_t mbar) {
    asm volatile(
        "cp.async.bulk.tensor.3d.shared::cta.global.tile.mbarrier::complete_tx::bytes "
        "[%0], [%1, {%2, %3, %4}], [%5];"
        :: "r"(dst), "l"(tmap), "r"(x), "r"(y), "r"(z), "r"(mbar) : "memory");
}
__device__ __forceinline__ void ldsm4(uint32_t* r, uint32_t addr) {
    asm volatile("ldmatrix.sync.aligned.m8n8.x4.shared.b16 {%0,%1,%2,%3}, [%4];"
        : "=r"(r[0]), "=r"(r[1]), "=r"(r[2]), "=r"(r[3]) : "r"(addr));
}
__device__ __forceinline__ void mma16816(float* d, const uint32_t* a, const uint32_t* b) {
    asm volatile("mma.sync.aligned.m16n8k16.row.col.f32.bf16.bf16.f32 "
        "{%0,%1,%2,%3}, {%4,%5,%6,%7}, {%8,%9}, {%0,%1,%2,%3};"
        : "+f"(d[0]), "+f"(d[1]), "+f"(d[2]), "+f"(d[3])
        : "r"(a[0]), "r"(a[1]), "r"(a[2]), "r"(a[3]), "r"(b[0]), "r"(b[1]));
}
__device__ __forceinline__ uint32_t swz(uint32_t base, int row, int byteCol) {
    return base + row * 128 + (byteCol ^ ((row & 7) << 4));
}

// ---------------- misc helpers ----------------
__device__ __forceinline__ unsigned int enc_f(float f) {
    unsigned int u = __float_as_uint(f);
    return (u & 0x80000000u) ? ~u : (u | 0x80000000u);
}
__device__ __forceinline__ float dec_f(unsigned int u) {
    u = (u & 0x80000000u) ? (u ^ 0x80000000u) : ~u;
    return __uint_as_float(u);
}
__device__ __forceinline__ void addh8(float* a, uint4 v) {
    const __half2* h = (const __half2*)&v;
    #pragma unroll
    for (int i = 0; i < 4; i++) {
        float2 f = __half22float2(h[i]);
        a[2 * i] += f.x;
        a[2 * i + 1] += f.y;
    }
}
__device__ __forceinline__ void pack_write_hi(__nv_bfloat16* __restrict__ apk, int v, int e,
                                              float r0, float r1, float r2, float r3) {
    int chunk = v >> 4;
    int pos = (v & 15) * 4;
    size_t base = ((size_t)chunk * N_EDGES + e) * 64 + pos;
    *(__nv_bfloat162*)(apk + base)     = __halves2bfloat162(__float2bfloat16(r0), __float2bfloat16(r1));
    *(__nv_bfloat162*)(apk + base + 2) = __halves2bfloat162(__float2bfloat16(r2), __float2bfloat16(r3));
}

// ---------------- setup kernels ----------------
__global__ void k_zero_meta(int* deg_e, int* deg_n, int* cur_e, int* cur_n,
                            unsigned int* maxbits, float* sumexp, float* out) {
    int i = blockIdx.x * blockDim.x + threadIdx.x;
    int stride = gridDim.x * blockDim.x;
    for (int j = i; j < N_NODES; j += stride) {
        deg_n[j] = 0; cur_n[j] = 0;
        if (j < N_EDGES) { deg_e[j] = 0; cur_e[j] = 0; }
        if (j < 128) out[j] = 0.0f;
        if (j == 0) { *maxbits = 0u; *sumexp = 0.0f; }
    }
}

__global__ void k_count(const int* __restrict__ nidx, const int* __restrict__ eidx,
                        int* deg_n, int* deg_e) {
    int i = blockIdx.x * blockDim.x + threadIdx.x;
    if (i < NNZ) {
        atomicAdd(&deg_e[eidx[i]], 1);
        atomicAdd(&deg_n[nidx[i]], 1);
    }
}

__global__ void k_scan_local(const int* __restrict__ deg, int* __restrict__ off,
                             int* __restrict__ bsum, int n) {
    __shared__ int sh[1024];
    int i = blockIdx.x * 1024 + threadIdx.x;
    int v = (i < n) ? deg[i] : 0;
    sh[threadIdx.x] = v;
    __syncthreads();
    #pragma unroll
    for (int s = 1; s < 1024; s <<= 1) {
        int t = (threadIdx.x >= (unsigned)s) ? sh[threadIdx.x - s] : 0;
        __syncthreads();
        sh[threadIdx.x] += t;
        __syncthreads();
    }
    if (i < n) off[i] = sh[threadIdx.x] - v;
    if (threadIdx.x == 1023) bsum[blockIdx.x] = sh[1023];
}

__global__ void k_carry(int* bsum, int nb, int* tot) {
    if (threadIdx.x == 0) {
        int s = 0;
        for (int i = 0; i < nb; i++) { int v = bsum[i]; bsum[i] = s; s += v; }
        *tot = s;
    }
}

__global__ void k_scan_add(int* __restrict__ off, const int* __restrict__ bsum,
                           const int* __restrict__ deg, float* __restrict__ inv, int n) {
    int i = blockIdx.x * blockDim.x + threadIdx.x;
    if (i < n) {
        off[i] += bsum[i >> 10];
        int d = deg[i];
        inv[i] = (d > 0) ? (1.0f / (float)d) : 0.0f;
    }
}

__global__ void k_fill_e(const int* __restrict__ nidx, const int* __restrict__ eidx,
                         const int* __restrict__ off_e, int* cur_e, int* csr_e) {
    int i = blockIdx.x * blockDim.x + threadIdx.x;
    if (i < NNZ) {
        int e = eidx[i];
        int p = atomicAdd(&cur_e[e], 1);
        csr_e[off_e[e] + p] = nidx[i];
    }
}

__global__ void k_fill_n(const int* __restrict__ nidx, const int* __restrict__ eidx,
                         const int* __restrict__ off_n, int* cur_n, int* csr_n) {
    int i = blockIdx.x * blockDim.x + threadIdx.x;
    if (i < NNZ) {
        int n = nidx[i];
        int q = atomicAdd(&cur_n[n], 1);
        csr_n[off_n[n] + q] = eidx[i];
    }
}

__global__ void k_cvtX(const float* __restrict__ x, __half* __restrict__ xh) {
    int m = blockIdx.x;
    int k = threadIdx.x;   // 320
    float v = (k < 300) ? x[(size_t)m * 300 + k] : 0.0f;
    xh[(size_t)m * 320 + k] = __float2half_rn(v);
}

__global__ void k_packW(const float* __restrict__ W, int K, int N, __nv_bfloat16* __restrict__ wpk) {
    int n = blockIdx.x;
    int k = threadIdx.x;   // 320 threads
    float a = (k < K) ? W[(size_t)k * N + n] : 0.0f;
    __nv_bfloat16 h = __float2bfloat16(a);
    float r = a - __bfloat162float(h);
    int chunk = k >> 6;
    int kk = k & 63;
    wpk[((size_t)chunk * 512 + n) * 64 + kk] = h;
    wpk[((size_t)chunk * 512 + 256 + n) * 64 + kk] = __float2bfloat16(r);
}

// ---------------- edge gather (fp16 source) + fused bf16 hi pack, MLP-8 ----------------
__global__ void k_edge_pack320(const __half* __restrict__ xh,
                               const int* __restrict__ off_e, const int* __restrict__ csr_e,
                               const float* __restrict__ binv, __nv_bfloat16* __restrict__ apk) {
    int w = (blockIdx.x * blockDim.x + threadIdx.x) >> 5;
    if (w >= N_EDGES) return;
    int lane = threadIdx.x & 31;
    float a[8] = {0, 0, 0, 0, 0, 0, 0, 0};
    float b[8] = {0, 0, 0, 0, 0, 0, 0, 0};
    bool hasB = lane < 8;
    int beg = off_e[w], end = off_e[w + 1];
    int m = beg;
    for (; m + 7 < end; m += 8) {
        int idx[8];
        #pragma unroll
        for (int i = 0; i < 8; i++) idx[i] = csr_e[m + i];
        uint4 va[8];
        #pragma unroll
        for (int i = 0; i < 8; i++)
            va[i] = ((const uint4*)(xh + (size_t)idx[i] * 320))[lane];
        uint4 vb[8];
        if (hasB) {
            #pragma unroll
            for (int i = 0; i < 8; i++)
                vb[i] = ((const uint4*)(xh + (size_t)idx[i] * 320))[lane + 32];
        }
        #pragma unroll
        for (int i = 0; i < 8; i++) addh8(a, va[i]);
        if (hasB) {
            #pragma unroll
            for (int i = 0; i < 8; i++) addh8(b, vb[i]);
        }
    }
    for (; m < end; m++) {
        const uint4* r0 = (const uint4*)(xh + (size_t)csr_e[m] * 320);
        addh8(a, r0[lane]);
        if (hasB) addh8(b, r0[lane + 32]);
    }
    float bi = binv[w];
    #pragma unroll
    for (int i = 0; i < 8; i++) { a[i] *= bi; b[i] *= bi; }
    pack_write_hi(apk, 2 * lane, w, a[0], a[1], a[2], a[3]);
    pack_write_hi(apk, 2 * lane + 1, w, a[4], a[5], a[6], a[7]);
    if (hasB) {
        pack_write_hi(apk, 64 + 2 * lane, w, b[0], b[1], b[2], b[3]);
        pack_write_hi(apk, 64 + 2 * lane + 1, w, b[4], b[5], b[6], b[7]);
    }
}

__global__ void k_edge_pack256(const __half* __restrict__ h,
                               const int* __restrict__ off_e, const int* __restrict__ csr_e,
                               const float* __restrict__ binv, __nv_bfloat16* __restrict__ apk) {
    int w = (blockIdx.x * blockDim.x + threadIdx.x) >> 5;
    if (w >= N_EDGES) return;
    int lane = threadIdx.x & 31;
    float a[8] = {0, 0, 0, 0, 0, 0, 0, 0};
    int beg = off_e[w], end = off_e[w + 1];
    int m = beg;
    for (; m + 7 < end; m += 8) {
        int idx[8];
        #pragma unroll
        for (int i = 0; i < 8; i++) idx[i] = csr_e[m + i];
        uint4 v[8];
        #pragma unroll
        for (int i = 0; i < 8; i++)
            v[i] = ((const uint4*)(h + (size_t)idx[i] * 256))[lane];
        #pragma unroll
        for (int i = 0; i < 8; i++) addh8(a, v[i]);
    }
    for (; m < end; m++)
        addh8(a, ((const uint4*)(h + (size_t)csr_e[m] * 256))[lane]);
    float bi = binv[w];
    #pragma unroll
    for (int i = 0; i < 8; i++) a[i] *= bi;
    pack_write_hi(apk, 2 * lane, w, a[0], a[1], a[2], a[3]);
    pack_write_hi(apk, 2 * lane + 1, w, a[4], a[5], a[6], a[7]);
}

// ---------------- TMA + mma.sync GEMM: A bf16, W = Whi + Wlo; fp16 out ----------------
#define STAGE_B 49152
#define N_STAGE 4
#define MB_OFF  (N_STAGE * STAGE_B)
#define SMEM_GEMM (MB_OFF + 64)

__global__ __launch_bounds__(256, 1) void k_mma_gemm(
    const __grid_constant__ CUtensorMap tmA,
    const __grid_constant__ CUtensorMap tmB,
    __half* __restrict__ C, int M, int Ncols, int chunks) {
    extern __shared__ char smem[];
    uint32_t sb = smem_u32(smem);
    int tid = threadIdx.x;
    int lane = tid & 31;
    int wid = tid >> 5;
    int wm = wid >> 2;
    int wn = wid & 3;
    int mBase = blockIdx.y * 128;
    int nBase = blockIdx.x * 128;

    if (tid == 0) {
        #pragma unroll
        for (int s = 0; s < N_STAGE; s++) MBAR_INIT(sb + MB_OFF + s * 8, 1);
    }
    __syncthreads();
    if (tid == 0) {
        #pragma unroll
        for (int s = 0; s < N_STAGE; s++) {
            if (s < chunks) {
                MBAR_EXPECT_TX(sb + MB_OFF + s * 8, STAGE_B);
                tma3d(sb + s * STAGE_B, &tmA, 0, mBase, s, sb + MB_OFF + s * 8);
                tma3d(sb + s * STAGE_B + 16384, &tmB, 0, nBase, s, sb + MB_OFF + s * 8);
                tma3d(sb + s * STAGE_B + 32768, &tmB, 0, nBase + 256, s, sb + MB_OFF + s * 8);
            }
        }
    }

    int a_row = lane & 15;
    int a_byte = (lane >> 4) << 4;
    int b_row = ((lane & 16) >> 1) + (lane & 7);
    int b_byte = (lane & 8) * 2;

    float acc[4][4][4];
    #pragma unroll
    for (int i = 0; i < 4; i++)
        #pragma unroll
        for (int j = 0; j < 4; j++)
            #pragma unroll
            for (int q = 0; q < 4; q++) acc[i][j][q] = 0.0f;

    for (int c = 0; c < chunks; c++) {
        int st = c & (N_STAGE - 1);
        MBAR_WAIT(sb + MB_OFF + st * 8, (c >> 2) & 1);
        uint32_t sA = sb + st * STAGE_B;
        uint32_t sBh = sA + 16384;
        uint32_t sBl = sA + 32768;
        #pragma unroll
        for (int ks = 0; ks < 4; ks++) {
            int kb = ks * 32;
            uint32_t ah[4][4], bh[2][4], bl[2][4];
            #pragma unroll
            for (int i = 0; i < 4; i++) {
                int r = wm * 64 + i * 16 + a_row;
                ldsm4(ah[i], swz(sA, r, kb + a_byte));
            }
            #pragma unroll
            for (int jj = 0; jj < 2; jj++) {
                int r = wn * 32 + jj * 16 + b_row;
                ldsm4(bh[jj], swz(sBh, r, kb + b_byte));
                ldsm4(bl[jj], swz(sBl, r, kb + b_byte));
            }
            #pragma unroll
            for (int i = 0; i < 4; i++)
                #pragma unroll
                for (int j = 0; j < 4; j++) {
                    const uint32_t* bH = &bh[j >> 1][(j & 1) * 2];
                    const uint32_t* bL = &bl[j >> 1][(j & 1) * 2];
                    mma16816(acc[i][j], ah[i], bH);
                    mma16816(acc[i][j], ah[i], bL);
                }
        }
        __syncthreads();
        if (tid == 0 && c + N_STAGE < chunks) {
            MBAR_EXPECT_TX(sb + MB_OFF + st * 8, STAGE_B);
            tma3d(sb + st * STAGE_B, &tmA, 0, mBase, c + N_STAGE, sb + MB_OFF + st * 8);
            tma3d(sb + st * STAGE_B + 16384, &tmB, 0, nBase, c + N_STAGE, sb + MB_OFF + st * 8);
            tma3d(sb + st * STAGE_B + 32768, &tmB, 0, nBase + 256, c + N_STAGE, sb + MB_OFF + st * 8);
        }
    }

    #pragma unroll
    for (int i = 0; i < 4; i++) {
        int r0 = mBase + wm * 64 + i * 16 + (lane >> 2);
        #pragma unroll
        for (int j = 0; j < 4; j++) {
            int cc = nBase + wn * 32 + j * 8 + (lane & 3) * 2;
            if (r0 < M)
                *(__half2*)&C[(size_t)r0 * Ncols + cc] =
                    __floats2half2_rn(acc[i][j][0], acc[i][j][1]);
            if (r0 + 8 < M)
                *(__half2*)&C[(size_t)(r0 + 8) * Ncols + cc] =
                    __floats2half2_rn(acc[i][j][2], acc[i][j][3]);
        }
    }
}

// ---------------- node gather, MLP-8 ----------------
__global__ void k_node_agg256(const __half* __restrict__ xwE,
                              const int* __restrict__ off_n, const int* __restrict__ csr_n,
                              const float* __restrict__ dinv, const float* __restrict__ bias,
                              __half* __restrict__ dst) {
    int w = (blockIdx.x * blockDim.x + threadIdx.x) >> 5;
    if (w >= N_NODES) return;
    int lane = threadIdx.x & 31;
    float a[8] = {0, 0, 0, 0, 0, 0, 0, 0};
    int beg = off_n[w], end = off_n[w + 1];
    int m = beg;
    for (; m + 7 < end; m += 8) {
        int idx[8];
        #pragma unroll
        for (int i = 0; i < 8; i++) idx[i] = csr_n[m + i];
        uint4 v[8];
        #pragma unroll
        for (int i = 0; i < 8; i++)
            v[i] = ((const uint4*)(xwE + (size_t)idx[i] * 256))[lane];
        #pragma unroll
        for (int i = 0; i < 8; i++) addh8(a, v[i]);
    }
    for (; m + 3 < end; m += 4) {
        int e0 = csr_n[m], e1 = csr_n[m + 1], e2 = csr_n[m + 2], e3 = csr_n[m + 3];
        uint4 v0 = ((const uint4*)(xwE + (size_t)e0 * 256))[lane];
        uint4 v1 = ((const uint4*)(xwE + (size_t)e1 * 256))[lane];
        uint4 v2 = ((const uint4*)(xwE + (size_t)e2 * 256))[lane];
        uint4 v3 = ((const uint4*)(xwE + (size_t)e3 * 256))[lane];
        addh8(a, v0); addh8(a, v1); addh8(a, v2); addh8(a, v3);
    }
    for (; m < end; m++)
        addh8(a, ((const uint4*)(xwE + (size_t)csr_n[m] * 256))[lane]);
    float di = dinv[w];
    float4 b0 = ((const float4*)bias)[2 * lane];
    float4 b1 = ((const float4*)bias)[2 * lane + 1];
    float r[8];
    r[0] = a[0] * di + b0.x; r[1] = a[1] * di + b0.y;
    r[2] = a[2] * di + b0.z; r[3] = a[3] * di + b0.w;
    r[4] = a[4] * di + b1.x; r[5] = a[5] * di + b1.y;
    r[6] = a[6] * di + b1.z; r[7] = a[7] * di + b1.w;
    #pragma unroll
    for (int i = 0; i < 8; i++) r[i] = r[i] > 0.f ? r[i] : 0.01f * r[i];
    __half2 o[4];
    #pragma unroll
    for (int i = 0; i < 4; i++) o[i] = __floats2half2_rn(r[2 * i], r[2 * i + 1]);
    ((uint4*)(dst + (size_t)w * 256))[lane] = *(const uint4*)o;
}

// ---------------- final-layer algebraic tail ----------------
__global__ void k_cdot(const float* __restrict__ b3, const float* __restrict__ aw,
                       const float* __restrict__ ab, float* __restrict__ cdot) {
    int f = threadIdx.x;   // 128
    float v = b3[f] * aw[f];
    #pragma unroll
    for (int o = 16; o; o >>= 1) v += __shfl_xor_sync(0xffffffffu, v, o);
    __shared__ float sm[4];
    if ((f & 31) == 0) sm[f >> 5] = v;
    __syncthreads();
    if (f == 0) *cdot = sm[0] + sm[1] + sm[2] + sm[3] + ab[0];
}

__global__ void k_edge_dot(const __half* __restrict__ xwE, const float* __restrict__ aw,
                           float* __restrict__ t) {
    int e = (blockIdx.x * blockDim.x + threadIdx.x) >> 5;
    if (e >= N_EDGES) return;
    int lane = threadIdx.x & 31;
    uint2 v = ((const uint2*)(xwE + (size_t)e * 128))[lane];
    const __half2* h = (const __half2*)&v;
    float2 f0 = __half22float2(h[0]);
    float2 f1 = __half22float2(h[1]);
    float4 wv = ((const float4*)aw)[lane];
    float d = f0.x * wv.x + f0.y * wv.y + f1.x * wv.z + f1.y * wv.w;
    #pragma unroll
    for (int o = 16; o; o >>= 1) d += __shfl_xor_sync(0xffffffffu, d, o);
    if (lane == 0) t[e] = d;
}

__global__ void k_logits_node(const float* __restrict__ t,
                              const int* __restrict__ off_n, const int* __restrict__ csr_n,
                              const float* __restrict__ dinv, const float* __restrict__ cdot,
                              float* __restrict__ logits, unsigned int* maxbits) {
    int n = blockIdx.x * blockDim.x + threadIdx.x;
    float lg = -3.4e38f;
    if (n < N_NODES) {
        float s = 0.f;
        int beg = off_n[n], end = off_n[n + 1];
        for (int m = beg; m < end; m++) s += t[csr_n[m]];
        lg = dinv[n] * s + *cdot;
        logits[n] = lg;
    }
    #pragma unroll
    for (int o = 16; o; o >>= 1) lg = fmaxf(lg, __shfl_xor_sync(0xffffffffu, lg, o));
    __shared__ float sm[8];
    if ((threadIdx.x & 31) == 0) sm[threadIdx.x >> 5] = lg;
    __syncthreads();
    if (threadIdx.x < 8) {
        float mv = sm[threadIdx.x];
        #pragma unroll
        for (int o = 4; o; o >>= 1) mv = fmaxf(mv, __shfl_xor_sync(0xffu, mv, o));
        if (threadIdx.x == 0) atomicMax(maxbits, enc_f(mv));
    }
}

__global__ void k_sumexp_coef(const float* __restrict__ logits,
                              const unsigned int* __restrict__ maxbits,
                              const float* __restrict__ dinv,
                              float* __restrict__ c, float* sumexp) {
    float mx = dec_f(*maxbits);
    int i = blockIdx.x * blockDim.x + threadIdx.x;
    int stride = gridDim.x * blockDim.x;
    float s = 0.f;
    for (int j = i; j < N_NODES; j += stride) {
        float ev = expf(logits[j] - mx);
        c[j] = ev * dinv[j];
        s += ev;
    }
    #pragma unroll
    for (int o = 16; o; o >>= 1) s += __shfl_xor_sync(0xffffffffu, s, o);
    __shared__ float sm[8];
    if ((threadIdx.x & 31) == 0) sm[threadIdx.x >> 5] = s;
    __syncthreads();
    if (threadIdx.x < 8) {
        float tt = sm[threadIdx.x];
        #pragma unroll
        for (int o = 4; o; o >>= 1) tt += __shfl_xor_sync(0xffu, tt, o);
        if (threadIdx.x == 0) atomicAdd(sumexp, tt);
    }
}

__global__ void k_edge_coef(const float* __restrict__ c,
                            const int* __restrict__ off_e, const int* __restrict__ csr_e,
                            float* __restrict__ s) {
    int e = (blockIdx.x * blockDim.x + threadIdx.x) >> 5;
    if (e >= N_EDGES) return;
    int lane = threadIdx.x & 31;
    float acc = 0.f;
    int beg = off_e[e], end = off_e[e + 1];
    for (int m = beg + lane; m < end; m += 32) acc += c[csr_e[m]];
    #pragma unroll
    for (int o = 16; o; o >>= 1) acc += __shfl_xor_sync(0xffffffffu, acc, o);
    if (lane == 0) s[e] = acc;
}

__global__ void k_final_sum(const __half* __restrict__ xwE, const float* __restrict__ s,
                            float* __restrict__ out) {
    int f = threadIdx.x;   // 128
    int e0 = blockIdx.x * 128;
    int e1 = min(e0 + 128, N_EDGES);
    float acc = 0.f;
    for (int e = e0; e < e1; e++)
        acc += s[e] * __half2float(xwE[(size_t)e * 128 + f]);
    atomicAdd(&out[f], acc);
}

__global__ void k_finalize(float* __restrict__ out, const float* __restrict__ sumexp,
                           const float* __restrict__ b3) {
    int f = threadIdx.x;
    out[f] = out[f] / (*sumexp) + b3[f];
}

// ---------------- host-side tensormap plumbing ----------------
typedef CUresult (*PFN_encodeTmap)(
    CUtensorMap*, CUtensorMapDataType, unsigned int, void*,
    const unsigned long long*, const unsigned long long*,
    const unsigned int*, const unsigned int*,
    CUtensorMapInterleave, CUtensorMapSwizzle, CUtensorMapL2promotion, CUtensorMapFloatOOBfill);

// ---------------- launch ----------------
extern "C" void kernel_launch(void* const* d_in, const int* in_sizes, int n_in,
                              void* d_out, int out_size) {
    const float* x   = (const float*)d_in[0];
    const int*   hei = (const int*)d_in[1];
    const int*   nidx = hei;
    const int*   eidx = hei + NNZ;
    const float* W1 = (const float*)d_in[2];
    const float* b1 = (const float*)d_in[3];
    const float* W2 = (const float*)d_in[4];
    const float* b2 = (const float*)d_in[5];
    const float* W3 = (const float*)d_in[6];
    const float* b3 = (const float*)d_in[7];
    const float* aw = (const float*)d_in[8];
    const float* ab = (const float*)d_in[9];
    float* out = (float*)d_out;

    static __half *p_xh = nullptr, *p_xwE, *p_h16, *p_h16b;
    static float *p_t, *p_s, *p_c, *p_cdot;
    static float *p_binv, *p_dinv, *p_logits, *p_sumexp;
    static int *p_deg_e, *p_deg_n, *p_off_e, *p_off_n, *p_cur_e, *p_cur_n, *p_csr_e, *p_csr_n;
    static int *p_bsum_e, *p_bsum_n;
    static unsigned int* p_maxbits;
    static __nv_bfloat16 *p_Apk, *p_Wpk;
    static CUtensorMap tmA, tmB1, tmB2, tmB3;
    static cudaStream_t s1;
    static cudaEvent_t evFork, evCnt, evPrep, evN;
    if (!p_xh) {
        cudaGetSymbolAddress((void**)&p_xh, g_xh);
        cudaGetSymbolAddress((void**)&p_xwE, g_xwE);
        cudaGetSymbolAddress((void**)&p_h16, g_h16);
        cudaGetSymbolAddress((void**)&p_h16b, g_h16b);
        cudaGetSymbolAddress((void**)&p_t, g_t);
        cudaGetSymbolAddress((void**)&p_s, g_s);
        cudaGetSymbolAddress((void**)&p_c, g_c);
        cudaGetSymbolAddress((void**)&p_cdot, g_cdot);
        cudaGetSymbolAddress((void**)&p_binv, g_binv);
        cudaGetSymbolAddress((void**)&p_dinv, g_dinv);
        cudaGetSymbolAddress((void**)&p_logits, g_logits);
        cudaGetSymbolAddress((void**)&p_sumexp, g_sumexp);
        cudaGetSymbolAddress((void**)&p_deg_e, g_deg_e);
        cudaGetSymbolAddress((void**)&p_deg_n, g_deg_n);
        cudaGetSymbolAddress((void**)&p_off_e, g_off_e);
        cudaGetSymbolAddress((void**)&p_off_n, g_off_n);
        cudaGetSymbolAddress((void**)&p_cur_e, g_cur_e);
        cudaGetSymbolAddress((void**)&p_cur_n, g_cur_n);
        cudaGetSymbolAddress((void**)&p_csr_e, g_csr_e);
        cudaGetSymbolAddress((void**)&p_csr_n, g_csr_n);
        cudaGetSymbolAddress((void**)&p_bsum_e, g_bsum_e);
        cudaGetSymbolAddress((void**)&p_bsum_n, g_bsum_n);
        cudaGetSymbolAddress((void**)&p_maxbits, g_maxbits);
        cudaGetSymbolAddress((void**)&p_Apk, g_Apk);
        cudaGetSymbolAddress((void**)&p_Wpk, g_Wpk);
        cudaFuncSetAttribute(k_mma_gemm, cudaFuncAttributeMaxDynamicSharedMemorySize, SMEM_GEMM);
        cudaStreamCreateWithFlags(&s1, cudaStreamNonBlocking);
        cudaEventCreateWithFlags(&evFork, cudaEventDisableTiming);
        cudaEventCreateWithFlags(&evCnt, cudaEventDisableTiming);
        cudaEventCreateWithFlags(&evPrep, cudaEventDisableTiming);
        cudaEventCreateWithFlags(&evN, cudaEventDisableTiming);

        void* fp = nullptr;
        cudaDriverEntryPointQueryResult qr;
        cudaGetDriverEntryPoint("cuTensorMapEncodeTiled", &fp, cudaEnableDefault, &qr);
        PFN_encodeTmap enc = (PFN_encodeTmap)fp;
        unsigned long long dimsA[3] = {128ull, (unsigned long long)N_EDGES, (unsigned long long)NCHUNK};
        unsigned long long strA[2]  = {128ull, 128ull * N_EDGES};
        unsigned long long dimsB[3] = {128ull, 512ull, (unsigned long long)NCHUNK};
        unsigned long long strB[2]  = {128ull, 128ull * 512ull};
        unsigned int box[3] = {128u, 128u, 1u};
        unsigned int est[3] = {1u, 1u, 1u};
        enc(&tmA, CU_TENSOR_MAP_DATA_TYPE_UINT8, 3, (void*)p_Apk, dimsA, strA, box, est,
            CU_TENSOR_MAP_INTERLEAVE_NONE, CU_TENSOR_MAP_SWIZZLE_128B,
            CU_TENSOR_MAP_L2_PROMOTION_L2_128B, CU_TENSOR_MAP_FLOAT_OOB_FILL_NONE);
        enc(&tmB1, CU_TENSOR_MAP_DATA_TYPE_UINT8, 3, (void*)(p_Wpk), dimsB, strB, box, est,
            CU_TENSOR_MAP_INTERLEAVE_NONE, CU_TENSOR_MAP_SWIZZLE_128B,
            CU_TENSOR_MAP_L2_PROMOTION_L2_128B, CU_TENSOR_MAP_FLOAT_OOB_FILL_NONE);
        enc(&tmB2, CU_TENSOR_MAP_DATA_TYPE_UINT8, 3, (void*)(p_Wpk + WPK_SLICE), dimsB, strB, box, est,
            CU_TENSOR_MAP_INTERLEAVE_NONE, CU_TENSOR_MAP_SWIZZLE_128B,
            CU_TENSOR_MAP_L2_PROMOTION_L2_128B, CU_TENSOR_MAP_FLOAT_OOB_FILL_NONE);
        enc(&tmB3, CU_TENSOR_MAP_DATA_TYPE_UINT8, 3, (void*)(p_Wpk + 2 * WPK_SLICE), dimsB, strB, box, est,
            CU_TENSOR_MAP_INTERLEAVE_NONE, CU_TENSOR_MAP_SWIZZLE_128B,
            CU_TENSOR_MAP_L2_PROMOTION_L2_128B, CU_TENSOR_MAP_FLOAT_OOB_FILL_NONE);
    }

    // ---- fork: conversions on s1; CSR edge-side on stream 0 ----
    cudaEventRecord(evFork, 0);
    cudaStreamWaitEvent(s1, evFork, 0);
    k_cvtX<<<N_NODES, 320, 0, s1>>>(x, p_xh);
    k_packW<<<256, 320, 0, s1>>>(W1, 300, 256, p_Wpk);
    k_packW<<<256, 320, 0, s1>>>(W2, 256, 256, p_Wpk + WPK_SLICE);
    k_packW<<<128, 320, 0, s1>>>(W3, 256, 128, p_Wpk + 2 * WPK_SLICE);
    k_cdot<<<1, 128, 0, s1>>>(b3, aw, ab, p_cdot);
    cudaEventRecord(evPrep, s1);

    k_zero_meta<<<400, 256>>>(p_deg_e, p_deg_n, p_cur_e, p_cur_n, p_maxbits, p_sumexp, out);
    k_count<<<(NNZ + 255) / 256, 256>>>(nidx, eidx, p_deg_n, p_deg_e);
    cudaEventRecord(evCnt, 0);

    const int NBE = (N_EDGES + 1023) / 1024;
    const int NBN = (N_NODES + 1023) / 1024;
    k_scan_local<<<NBE, 1024>>>(p_deg_e, p_off_e, p_bsum_e, N_EDGES);
    k_carry<<<1, 32>>>(p_bsum_e, NBE, p_off_e + N_EDGES);
    k_scan_add<<<(N_EDGES + 255) / 256, 256>>>(p_off_e, p_bsum_e, p_deg_e, p_binv, N_EDGES);
    k_fill_e<<<(NNZ + 255) / 256, 256>>>(nidx, eidx, p_off_e, p_cur_e, p_csr_e);

    cudaStreamWaitEvent(s1, evCnt, 0);
    k_scan_local<<<NBN, 1024, 0, s1>>>(p_deg_n, p_off_n, p_bsum_n, N_NODES);
    k_carry<<<1, 32, 0, s1>>>(p_bsum_n, NBN, p_off_n + N_NODES);
    k_scan_add<<<(N_NODES + 255) / 256, 256, 0, s1>>>(p_off_n, p_bsum_n, p_deg_n, p_dinv, N_NODES);
    k_fill_n<<<(NNZ + 255) / 256, 256, 0, s1>>>(nidx, eidx, p_off_n, p_cur_n, p_csr_n);
    cudaEventRecord(evN, s1);

    cudaStreamWaitEvent(0, evPrep, 0);

    const int EB = (N_EDGES * 32) / 256;    // 2500
    const int NB = (N_NODES * 32) / 256;    // 12500
    const int GM = (N_EDGES + 127) / 128;   // 157

    // ---- layer 1 ----
    k_edge_pack320<<<EB, 256>>>(p_xh, p_off_e, p_csr_e, p_binv, p_Apk);
    k_mma_gemm<<<dim3(2, GM), 256, SMEM_GEMM>>>(tmA, tmB1, p_xwE, N_EDGES, 256, 5);
    cudaStreamWaitEvent(0, evN, 0);
    k_node_agg256<<<NB, 256>>>(p_xwE, p_off_n, p_csr_n, p_dinv, b1, p_h16);

    // ---- layer 2 ----
    k_edge_pack256<<<EB, 256>>>(p_h16, p_off_e, p_csr_e, p_binv, p_Apk);
    k_mma_gemm<<<dim3(2, GM), 256, SMEM_GEMM>>>(tmA, tmB2, p_xwE, N_EDGES, 256, 4);
    k_node_agg256<<<NB, 256>>>(p_xwE, p_off_n, p_csr_n, p_dinv, b2, p_h16b);

    // ---- layer 3: edge GEMM then algebraic pooling tail ----
    k_edge_pack256<<<EB, 256>>>(p_h16b, p_off_e, p_csr_e, p_binv, p_Apk);
    k_mma_gemm<<<dim3(1, GM), 256, SMEM_GEMM>>>(tmA, tmB3, p_xwE, N_EDGES, 128, 4);
    k_edge_dot<<<EB, 256>>>(p_xwE, aw, p_t);
    k_logits_node<<<(N_NODES + 255) / 256, 256>>>(p_t, p_off_n, p_csr_n, p_dinv, p_cdot,
                                                  p_logits, p_maxbits);
    k_sumexp_coef<<<512, 256>>>(p_logits, p_maxbits, p_dinv, p_c, p_sumexp);
    k_edge_coef<<<EB, 256>>>(p_c, p_off_e, p_csr_e, p_s);
    k_final_sum<<<GM, 128>>>(p_xwE, p_s, out);
    k_finalize<<<1, 128>>>(out, p_sumexp, b3);
}

// round 16
// speedup vs baseline: 1.0985x; 1.0173x over previous
#include <cuda_runtime.h>
#include <cuda.h>
#include <cuda_bf16.h>
#include <cuda_fp16.h>
#include <math.h>
#include <stdint.h>

#define N_NODES 100000
#define N_EDGES 20000
#define NNZ     1600000
#define NCHUNK  5           // 5 chunks of 64 k => KPAD 320

// ---------------- scratch ----------------
__device__ __align__(128) __half g_xh[(size_t)N_NODES * 320];
__device__ __align__(128) __half g_xwE[(size_t)N_EDGES * 256];
__device__ __align__(128) __half g_h16[(size_t)N_NODES * 256];
__device__ __align__(128) __half g_h16b[(size_t)N_NODES * 256];
__device__ float g_t[N_EDGES];
__device__ float g_s[N_EDGES];
__device__ float g_c[N_NODES];
__device__ float g_cdot;
__device__ __align__(1024) __nv_bfloat16 g_Apk[(size_t)NCHUNK * N_EDGES * 64];
#define WPK_SLICE ((size_t)NCHUNK * 512 * 64)
__device__ __align__(1024) __nv_bfloat16 g_Wpk[3 * WPK_SLICE];

__device__ int   g_deg_e[N_EDGES];
__device__ int   g_deg_n[N_NODES];
__device__ float g_binv[N_EDGES];
__device__ float g_dinv[N_NODES];
__device__ int   g_off_e[N_EDGES + 1];
__device__ int   g_off_n[N_NODES + 1];
__device__ int   g_cur_e[N_EDGES];
__device__ int   g_cur_n[N_NODES];
__device__ int   g_csr_e[NNZ];
__device__ int   g_csr_n[NNZ];
__device__ int   g_bsum_e[64];
__device__ int   g_bsum_n[128];

__device__ float        g_logits[N_NODES];
__device__ unsigned int g_maxbits;
__device__ float        g_sumexp;

// ---------------- PTX helpers ----------------
__device__ __forceinline__ uint32_t smem_u32(const void* p) {
    uint32_t a;
    asm("{ .reg .u64 t; cvta.to.shared.u64 t, %1; cvt.u32.u64 %0, t; }" : "=r"(a) : "l"(p));
    return a;
}
#define MBAR_INIT(a, cnt) asm volatile("mbarrier.init.shared.b64 [%0], %1;" :: "r"(a), "r"(cnt) : "memory")
#define MBAR_EXPECT_TX(a, b) asm volatile("mbarrier.arrive.expect_tx.shared.b64 _, [%0], %1;" :: "r"(a), "r"(b) : "memory")
#define MBAR_WAIT(a, par) do {                                             \
    uint32_t _m = (a); uint32_t _p = (par); uint32_t _d;                   \
    asm volatile("{\n .reg .pred p;\n"                                     \
        " mbarrier.try_wait.parity.acquire.cta.shared::cta.b64 p, [%1], %2;\n" \
        " selp.b32 %0,1,0,p;\n}" : "=r"(_d) : "r"(_m), "r"(_p) : "memory");\
    if (!_d) {                                                             \
        asm volatile("{\n .reg .pred P1;\n"                                \
        "W_%=:\n mbarrier.try_wait.parity.acquire.cta.shared::cta.b64 P1, [%0], %1, 0x989680;\n" \
        " @P1 bra.uni D_%=;\n bra.uni W_%=;\nD_%=:\n}"                     \
        :: "r"(_m), "r"(_p) : "memory");                                   \
    } } while (0)

__device__ __forceinline__ void tma3d(uint32_t dst, const void* tmap, int x, int y, int z, uint32_t mbar) {
    asm volatile(
        "cp.async.bulk.tensor.3d.shared::cta.global.tile.mbarrier::complete_tx::bytes "
        "[%0], [%1, {%2, %3, %4}], [%5];"
        :: "r"(dst), "l"(tmap), "r"(x), "r"(y), "r"(z), "r"(mbar) : "memory");
}
__device__ __forceinline__ void ldsm4(uint32_t* r, uint32_t addr) {
    asm volatile("ldmatrix.sync.aligned.m8n8.x4.shared.b16 {%0,%1,%2,%3}, [%4];"
        : "=r"(r[0]), "=r"(r[1]), "=r"(r[2]), "=r"(r[3]) : "r"(addr));
}
__device__ __forceinline__ void mma16816(float* d, const uint32_t* a, const uint32_t* b) {
    asm volatile("mma.sync.aligned.m16n8k16.row.col.f32.bf16.bf16.f32 "
        "{%0,%1,%2,%3}, {%4,%5,%6,%7}, {%8,%9}, {%0,%1,%2,%3};"
        : "+f"(d[0]), "+f"(d[1]), "+f"(d[2]), "+f"(d[3])
        : "r"(a[0]), "r"(a[1]), "r"(a[2]), "r"(a[3]), "r"(b[0]), "r"(b[1]));
}
__device__ __forceinline__ uint32_t swz(uint32_t base, int row, int byteCol) {
    return base + row * 128 + (byteCol ^ ((row & 7) << 4));
}

// ---------------- misc helpers ----------------
__device__ __forceinline__ unsigned int enc_f(float f) {
    unsigned int u = __float_as_uint(f);
    return (u & 0x80000000u) ? ~u : (u | 0x80000000u);
}
__device__ __forceinline__ float dec_f(unsigned int u) {
    u = (u & 0x80000000u) ? (u ^ 0x80000000u) : ~u;
    return __uint_as_float(u);
}
__device__ __forceinline__ void addh8(float* a, uint4 v) {
    const __half2* h = (const __half2*)&v;
    #pragma unroll
    for (int i = 0; i < 4; i++) {
        float2 f = __half22float2(h[i]);
        a[2 * i] += f.x;
        a[2 * i + 1] += f.y;
    }
}
__device__ __forceinline__ void pack_write_hi(__nv_bfloat16* __restrict__ apk, int v, int e,
                                              float r0, float r1, float r2, float r3) {
    int chunk = v >> 4;
    int pos = (v & 15) * 4;
    size_t base = ((size_t)chunk * N_EDGES + e) * 64 + pos;
    *(__nv_bfloat162*)(apk + base)     = __halves2bfloat162(__float2bfloat16(r0), __float2bfloat16(r1));
    *(__nv_bfloat162*)(apk + base + 2) = __halves2bfloat162(__float2bfloat16(r2), __float2bfloat16(r3));
}

// ---------------- setup kernels ----------------
__global__ void k_zero_meta(int* deg_e, int* deg_n, int* cur_e, int* cur_n,
                            unsigned int* maxbits, float* sumexp, float* out) {
    int i = blockIdx.x * blockDim.x + threadIdx.x;
    int stride = gridDim.x * blockDim.x;
    for (int j = i; j < N_NODES; j += stride) {
        deg_n[j] = 0; cur_n[j] = 0;
        if (j < N_EDGES) { deg_e[j] = 0; cur_e[j] = 0; }
        if (j < 128) out[j] = 0.0f;
        if (j == 0) { *maxbits = 0u; *sumexp = 0.0f; }
    }
}

__global__ void k_count(const int* __restrict__ nidx, const int* __restrict__ eidx,
                        int* deg_n, int* deg_e) {
    int i = blockIdx.x * blockDim.x + threadIdx.x;
    if (i < NNZ) {
        atomicAdd(&deg_e[eidx[i]], 1);
        atomicAdd(&deg_n[nidx[i]], 1);
    }
}

__global__ void k_scan_local(const int* __restrict__ deg, int* __restrict__ off,
                             int* __restrict__ bsum, int n) {
    __shared__ int sh[1024];
    int i = blockIdx.x * 1024 + threadIdx.x;
    int v = (i < n) ? deg[i] : 0;
    sh[threadIdx.x] = v;
    __syncthreads();
    #pragma unroll
    for (int s = 1; s < 1024; s <<= 1) {
        int t = (threadIdx.x >= (unsigned)s) ? sh[threadIdx.x - s] : 0;
        __syncthreads();
        sh[threadIdx.x] += t;
        __syncthreads();
    }
    if (i < n) off[i] = sh[threadIdx.x] - v;
    if (threadIdx.x == 1023) bsum[blockIdx.x] = sh[1023];
}

__global__ void k_carry(int* bsum, int nb, int* tot) {
    if (threadIdx.x == 0) {
        int s = 0;
        for (int i = 0; i < nb; i++) { int v = bsum[i]; bsum[i] = s; s += v; }
        *tot = s;
    }
}

__global__ void k_scan_add(int* __restrict__ off, const int* __restrict__ bsum,
                           const int* __restrict__ deg, float* __restrict__ inv, int n) {
    int i = blockIdx.x * blockDim.x + threadIdx.x;
    if (i < n) {
        off[i] += bsum[i >> 10];
        int d = deg[i];
        inv[i] = (d > 0) ? (1.0f / (float)d) : 0.0f;
    }
}

__global__ void k_fill_e(const int* __restrict__ nidx, const int* __restrict__ eidx,
                         const int* __restrict__ off_e, int* cur_e, int* csr_e) {
    int i = blockIdx.x * blockDim.x + threadIdx.x;
    if (i < NNZ) {
        int e = eidx[i];
        int p = atomicAdd(&cur_e[e], 1);
        csr_e[off_e[e] + p] = nidx[i];
    }
}

__global__ void k_fill_n(const int* __restrict__ nidx, const int* __restrict__ eidx,
                         const int* __restrict__ off_n, int* cur_n, int* csr_n) {
    int i = blockIdx.x * blockDim.x + threadIdx.x;
    if (i < NNZ) {
        int n = nidx[i];
        int q = atomicAdd(&cur_n[n], 1);
        csr_n[off_n[n] + q] = eidx[i];
    }
}

__global__ void k_cvtX(const float* __restrict__ x, __half* __restrict__ xh) {
    int m = blockIdx.x;
    int k = threadIdx.x;   // 320
    float v = (k < 300) ? x[(size_t)m * 300 + k] : 0.0f;
    xh[(size_t)m * 320 + k] = __float2half_rn(v);
}

__global__ void k_packW(const float* __restrict__ W, int K, int N, __nv_bfloat16* __restrict__ wpk) {
    int n = blockIdx.x;
    int k = threadIdx.x;   // 320 threads
    float a = (k < K) ? W[(size_t)k * N + n] : 0.0f;
    __nv_bfloat16 h = __float2bfloat16(a);
    float r = a - __bfloat162float(h);
    int chunk = k >> 6;
    int kk = k & 63;
    wpk[((size_t)chunk * 512 + n) * 64 + kk] = h;
    wpk[((size_t)chunk * 512 + 256 + n) * 64 + kk] = __float2bfloat16(r);
}

// ---------------- edge gather (fp16 source) + fused bf16 hi pack, MLP-8 ----------------
__global__ void k_edge_pack320(const __half* __restrict__ xh,
                               const int* __restrict__ off_e, const int* __restrict__ csr_e,
                               const float* __restrict__ binv, __nv_bfloat16* __restrict__ apk) {
    int w = (blockIdx.x * blockDim.x + threadIdx.x) >> 5;
    if (w >= N_EDGES) return;
    int lane = threadIdx.x & 31;
    float a[8] = {0, 0, 0, 0, 0, 0, 0, 0};
    float b[8] = {0, 0, 0, 0, 0, 0, 0, 0};
    bool hasB = lane < 8;
    int beg = off_e[w], end = off_e[w + 1];
    int m = beg;
    for (; m + 7 < end; m += 8) {
        int idx[8];
        #pragma unroll
        for (int i = 0; i < 8; i++) idx[i] = csr_e[m + i];
        uint4 va[8];
        #pragma unroll
        for (int i = 0; i < 8; i++)
            va[i] = ((const uint4*)(xh + (size_t)idx[i] * 320))[lane];
        uint4 vb[8];
        if (hasB) {
            #pragma unroll
            for (int i = 0; i < 8; i++)
                vb[i] = ((const uint4*)(xh + (size_t)idx[i] * 320))[lane + 32];
        }
        #pragma unroll
        for (int i = 0; i < 8; i++) addh8(a, va[i]);
        if (hasB) {
            #pragma unroll
            for (int i = 0; i < 8; i++) addh8(b, vb[i]);
        }
    }
    for (; m < end; m++) {
        const uint4* r0 = (const uint4*)(xh + (size_t)csr_e[m] * 320);
        addh8(a, r0[lane]);
        if (hasB) addh8(b, r0[lane + 32]);
    }
    float bi = binv[w];
    #pragma unroll
    for (int i = 0; i < 8; i++) { a[i] *= bi; b[i] *= bi; }
    pack_write_hi(apk, 2 * lane, w, a[0], a[1], a[2], a[3]);
    pack_write_hi(apk, 2 * lane + 1, w, a[4], a[5], a[6], a[7]);
    if (hasB) {
        pack_write_hi(apk, 64 + 2 * lane, w, b[0], b[1], b[2], b[3]);
        pack_write_hi(apk, 64 + 2 * lane + 1, w, b[4], b[5], b[6], b[7]);
    }
}

__global__ void k_edge_pack256(const __half* __restrict__ h,
                               const int* __restrict__ off_e, const int* __restrict__ csr_e,
                               const float* __restrict__ binv, __nv_bfloat16* __restrict__ apk) {
    int w = (blockIdx.x * blockDim.x + threadIdx.x) >> 5;
    if (w >= N_EDGES) return;
    int lane = threadIdx.x & 31;
    float a[8] = {0, 0, 0, 0, 0, 0, 0, 0};
    int beg = off_e[w], end = off_e[w + 1];
    int m = beg;
    for (; m + 7 < end; m += 8) {
        int idx[8];
        #pragma unroll
        for (int i = 0; i < 8; i++) idx[i] = csr_e[m + i];
        uint4 v[8];
        #pragma unroll
        for (int i = 0; i < 8; i++)
            v[i] = ((const uint4*)(h + (size_t)idx[i] * 256))[lane];
        #pragma unroll
        for (int i = 0; i < 8; i++) addh8(a, v[i]);
    }
    for (; m < end; m++)
        addh8(a, ((const uint4*)(h + (size_t)csr_e[m] * 256))[lane]);
    float bi = binv[w];
    #pragma unroll
    for (int i = 0; i < 8; i++) a[i] *= bi;
    pack_write_hi(apk, 2 * lane, w, a[0], a[1], a[2], a[3]);
    pack_write_hi(apk, 2 * lane + 1, w, a[4], a[5], a[6], a[7]);
}

// ---------------- TMA + mma.sync GEMM: A bf16, W = Whi + Wlo; fp16 out ----------------
// N_STAGE=2 -> 96KB smem/CTA -> 2 CTAs/SM (wave quantization fix)
#define STAGE_B 49152
#define N_STAGE 2
#define MB_OFF  (N_STAGE * STAGE_B)
#define SMEM_GEMM (MB_OFF + 64)

__global__ __launch_bounds__(256) void k_mma_gemm(
    const __grid_constant__ CUtensorMap tmA,
    const __grid_constant__ CUtensorMap tmB,
    __half* __restrict__ C, int M, int Ncols, int chunks) {
    extern __shared__ char smem[];
    uint32_t sb = smem_u32(smem);
    int tid = threadIdx.x;
    int lane = tid & 31;
    int wid = tid >> 5;
    int wm = wid >> 2;
    int wn = wid & 3;
    int mBase = blockIdx.y * 128;
    int nBase = blockIdx.x * 128;

    if (tid == 0) {
        #pragma unroll
        for (int s = 0; s < N_STAGE; s++) MBAR_INIT(sb + MB_OFF + s * 8, 1);
    }
    __syncthreads();
    if (tid == 0) {
        #pragma unroll
        for (int s = 0; s < N_STAGE; s++) {
            if (s < chunks) {
                MBAR_EXPECT_TX(sb + MB_OFF + s * 8, STAGE_B);
                tma3d(sb + s * STAGE_B, &tmA, 0, mBase, s, sb + MB_OFF + s * 8);
                tma3d(sb + s * STAGE_B + 16384, &tmB, 0, nBase, s, sb + MB_OFF + s * 8);
                tma3d(sb + s * STAGE_B + 32768, &tmB, 0, nBase + 256, s, sb + MB_OFF + s * 8);
            }
        }
    }

    int a_row = lane & 15;
    int a_byte = (lane >> 4) << 4;
    int b_row = ((lane & 16) >> 1) + (lane & 7);
    int b_byte = (lane & 8) * 2;

    float acc[4][4][4];
    #pragma unroll
    for (int i = 0; i < 4; i++)
        #pragma unroll
        for (int j = 0; j < 4; j++)
            #pragma unroll
            for (int q = 0; q < 4; q++) acc[i][j][q] = 0.0f;

    for (int c = 0; c < chunks; c++) {
        int st = c & (N_STAGE - 1);
        MBAR_WAIT(sb + MB_OFF + st * 8, (c >> 1) & 1);
        uint32_t sA = sb + st * STAGE_B;
        uint32_t sBh = sA + 16384;
        uint32_t sBl = sA + 32768;
        #pragma unroll
        for (int ks = 0; ks < 4; ks++) {
            int kb = ks * 32;
            uint32_t ah[4][4], bh[2][4], bl[2][4];
            #pragma unroll
            for (int i = 0; i < 4; i++) {
                int r = wm * 64 + i * 16 + a_row;
                ldsm4(ah[i], swz(sA, r, kb + a_byte));
            }
            #pragma unroll
            for (int jj = 0; jj < 2; jj++) {
                int r = wn * 32 + jj * 16 + b_row;
                ldsm4(bh[jj], swz(sBh, r, kb + b_byte));
                ldsm4(bl[jj], swz(sBl, r, kb + b_byte));
            }
            #pragma unroll
            for (int i = 0; i < 4; i++)
                #pragma unroll
                for (int j = 0; j < 4; j++) {
                    const uint32_t* bH = &bh[j >> 1][(j & 1) * 2];
                    const uint32_t* bL = &bl[j >> 1][(j & 1) * 2];
                    mma16816(acc[i][j], ah[i], bH);
                    mma16816(acc[i][j], ah[i], bL);
                }
        }
        __syncthreads();
        if (tid == 0 && c + N_STAGE < chunks) {
            MBAR_EXPECT_TX(sb + MB_OFF + st * 8, STAGE_B);
            tma3d(sb + st * STAGE_B, &tmA, 0, mBase, c + N_STAGE, sb + MB_OFF + st * 8);
            tma3d(sb + st * STAGE_B + 16384, &tmB, 0, nBase, c + N_STAGE, sb + MB_OFF + st * 8);
            tma3d(sb + st * STAGE_B + 32768, &tmB, 0, nBase + 256, c + N_STAGE, sb + MB_OFF + st * 8);
        }
    }

    #pragma unroll
    for (int i = 0; i < 4; i++) {
        int r0 = mBase + wm * 64 + i * 16 + (lane >> 2);
        #pragma unroll
        for (int j = 0; j < 4; j++) {
            int cc = nBase + wn * 32 + j * 8 + (lane & 3) * 2;
            if (r0 < M)
                *(__half2*)&C[(size_t)r0 * Ncols + cc] =
                    __floats2half2_rn(acc[i][j][0], acc[i][j][1]);
            if (r0 + 8 < M)
                *(__half2*)&C[(size_t)(r0 + 8) * Ncols + cc] =
                    __floats2half2_rn(acc[i][j][2], acc[i][j][3]);
        }
    }
}

// ---------------- node gather, MLP-8 ----------------
__global__ void k_node_agg256(const __half* __restrict__ xwE,
                              const int* __restrict__ off_n, const int* __restrict__ csr_n,
                              const float* __restrict__ dinv, const float* __restrict__ bias,
                              __half* __restrict__ dst) {
    int w = (blockIdx.x * blockDim.x + threadIdx.x) >> 5;
    if (w >= N_NODES) return;
    int lane = threadIdx.x & 31;
    float a[8] = {0, 0, 0, 0, 0, 0, 0, 0};
    int beg = off_n[w], end = off_n[w + 1];
    int m = beg;
    for (; m + 7 < end; m += 8) {
        int idx[8];
        #pragma unroll
        for (int i = 0; i < 8; i++) idx[i] = csr_n[m + i];
        uint4 v[8];
        #pragma unroll
        for (int i = 0; i < 8; i++)
            v[i] = ((const uint4*)(xwE + (size_t)idx[i] * 256))[lane];
        #pragma unroll
        for (int i = 0; i < 8; i++) addh8(a, v[i]);
    }
    for (; m + 3 < end; m += 4) {
        int e0 = csr_n[m], e1 = csr_n[m + 1], e2 = csr_n[m + 2], e3 = csr_n[m + 3];
        uint4 v0 = ((const uint4*)(xwE + (size_t)e0 * 256))[lane];
        uint4 v1 = ((const uint4*)(xwE + (size_t)e1 * 256))[lane];
        uint4 v2 = ((const uint4*)(xwE + (size_t)e2 * 256))[lane];
        uint4 v3 = ((const uint4*)(xwE + (size_t)e3 * 256))[lane];
        addh8(a, v0); addh8(a, v1); addh8(a, v2); addh8(a, v3);
    }
    for (; m < end; m++)
        addh8(a, ((const uint4*)(xwE + (size_t)csr_n[m] * 256))[lane]);
    float di = dinv[w];
    float4 b0 = ((const float4*)bias)[2 * lane];
    float4 b1 = ((const float4*)bias)[2 * lane + 1];
    float r[8];
    r[0] = a[0] * di + b0.x; r[1] = a[1] * di + b0.y;
    r[2] = a[2] * di + b0.z; r[3] = a[3] * di + b0.w;
    r[4] = a[4] * di + b1.x; r[5] = a[5] * di + b1.y;
    r[6] = a[6] * di + b1.z; r[7] = a[7] * di + b1.w;
    #pragma unroll
    for (int i = 0; i < 8; i++) r[i] = r[i] > 0.f ? r[i] : 0.01f * r[i];
    __half2 o[4];
    #pragma unroll
    for (int i = 0; i < 4; i++) o[i] = __floats2half2_rn(r[2 * i], r[2 * i + 1]);
    ((uint4*)(dst + (size_t)w * 256))[lane] = *(const uint4*)o;
}

// ---------------- final-layer algebraic tail ----------------
__global__ void k_cdot(const float* __restrict__ b3, const float* __restrict__ aw,
                       const float* __restrict__ ab, float* __restrict__ cdot) {
    int f = threadIdx.x;   // 128
    float v = b3[f] * aw[f];
    #pragma unroll
    for (int o = 16; o; o >>= 1) v += __shfl_xor_sync(0xffffffffu, v, o);
    __shared__ float sm[4];
    if ((f & 31) == 0) sm[f >> 5] = v;
    __syncthreads();
    if (f == 0) *cdot = sm[0] + sm[1] + sm[2] + sm[3] + ab[0];
}

__global__ void k_edge_dot(const __half* __restrict__ xwE, const float* __restrict__ aw,
                           float* __restrict__ t) {
    int e = (blockIdx.x * blockDim.x + threadIdx.x) >> 5;
    if (e >= N_EDGES) return;
    int lane = threadIdx.x & 31;
    uint2 v = ((const uint2*)(xwE + (size_t)e * 128))[lane];
    const __half2* h = (const __half2*)&v;
    float2 f0 = __half22float2(h[0]);
    float2 f1 = __half22float2(h[1]);
    float4 wv = ((const float4*)aw)[lane];
    float d = f0.x * wv.x + f0.y * wv.y + f1.x * wv.z + f1.y * wv.w;
    #pragma unroll
    for (int o = 16; o; o >>= 1) d += __shfl_xor_sync(0xffffffffu, d, o);
    if (lane == 0) t[e] = d;
}

__global__ void k_logits_node(const float* __restrict__ t,
                              const int* __restrict__ off_n, const int* __restrict__ csr_n,
                              const float* __restrict__ dinv, const float* __restrict__ cdot,
                              float* __restrict__ logits, unsigned int* maxbits) {
    int n = blockIdx.x * blockDim.x + threadIdx.x;
    float lg = -3.4e38f;
    if (n < N_NODES) {
        float s = 0.f;
        int beg = off_n[n], end = off_n[n + 1];
        int m = beg;
        for (; m + 7 < end; m += 8) {
            int idx[8];
            #pragma unroll
            for (int i = 0; i < 8; i++) idx[i] = csr_n[m + i];
            float tv[8];
            #pragma unroll
            for (int i = 0; i < 8; i++) tv[i] = t[idx[i]];
            #pragma unroll
            for (int i = 0; i < 8; i++) s += tv[i];
        }
        for (; m < end; m++) s += t[csr_n[m]];
        lg = dinv[n] * s + *cdot;
        logits[n] = lg;
    }
    #pragma unroll
    for (int o = 16; o; o >>= 1) lg = fmaxf(lg, __shfl_xor_sync(0xffffffffu, lg, o));
    __shared__ float sm[8];
    if ((threadIdx.x & 31) == 0) sm[threadIdx.x >> 5] = lg;
    __syncthreads();
    if (threadIdx.x < 8) {
        float mv = sm[threadIdx.x];
        #pragma unroll
        for (int o = 4; o; o >>= 1) mv = fmaxf(mv, __shfl_xor_sync(0xffu, mv, o));
        if (threadIdx.x == 0) atomicMax(maxbits, enc_f(mv));
    }
}

__global__ void k_sumexp_coef(const float* __restrict__ logits,
                              const unsigned int* __restrict__ maxbits,
                              const float* __restrict__ dinv,
                              float* __restrict__ c, float* sumexp) {
    float mx = dec_f(*maxbits);
    int i = blockIdx.x * blockDim.x + threadIdx.x;
    int stride = gridDim.x * blockDim.x;
    float s = 0.f;
    for (int j = i; j < N_NODES; j += stride) {
        float ev = expf(logits[j] - mx);
        c[j] = ev * dinv[j];
        s += ev;
    }
    #pragma unroll
    for (int o = 16; o; o >>= 1) s += __shfl_xor_sync(0xffffffffu, s, o);
    __shared__ float sm[8];
    if ((threadIdx.x & 31) == 0) sm[threadIdx.x >> 5] = s;
    __syncthreads();
    if (threadIdx.x < 8) {
        float tt = sm[threadIdx.x];
        #pragma unroll
        for (int o = 4; o; o >>= 1) tt += __shfl_xor_sync(0xffu, tt, o);
        if (threadIdx.x == 0) atomicAdd(sumexp, tt);
    }
}

__global__ void k_edge_coef(const float* __restrict__ c,
                            const int* __restrict__ off_e, const int* __restrict__ csr_e,
                            float* __restrict__ s) {
    int e = (blockIdx.x * blockDim.x + threadIdx.x) >> 5;
    if (e >= N_EDGES) return;
    int lane = threadIdx.x & 31;
    float acc = 0.f;
    int beg = off_e[e], end = off_e[e + 1];
    int m = beg + lane;
    for (; m + 96 < end; m += 128) {
        int i0 = csr_e[m], i1 = csr_e[m + 32], i2 = csr_e[m + 64], i3 = csr_e[m + 96];
        float c0 = c[i0], c1 = c[i1], c2 = c[i2], c3 = c[i3];
        acc += (c0 + c1) + (c2 + c3);
    }
    for (; m < end; m += 32) acc += c[csr_e[m]];
    #pragma unroll
    for (int o = 16; o; o >>= 1) acc += __shfl_xor_sync(0xffffffffu, acc, o);
    if (lane == 0) s[e] = acc;
}

__global__ void k_final_sum(const __half* __restrict__ xwE, const float* __restrict__ s,
                            float* __restrict__ out) {
    int f = threadIdx.x;   // 128
    int e0 = blockIdx.x * 128;
    int e1 = min(e0 + 128, N_EDGES);
    float acc = 0.f;
    for (int e = e0; e < e1; e++)
        acc += s[e] * __half2float(xwE[(size_t)e * 128 + f]);
    atomicAdd(&out[f], acc);
}

__global__ void k_finalize(float* __restrict__ out, const float* __restrict__ sumexp,
                           const float* __restrict__ b3) {
    int f = threadIdx.x;
    out[f] = out[f] / (*sumexp) + b3[f];
}

// ---------------- host-side tensormap plumbing ----------------
typedef CUresult (*PFN_encodeTmap)(
    CUtensorMap*, CUtensorMapDataType, unsigned int, void*,
    const unsigned long long*, const unsigned long long*,
    const unsigned int*, const unsigned int*,
    CUtensorMapInterleave, CUtensorMapSwizzle, CUtensorMapL2promotion, CUtensorMapFloatOOBfill);

// ---------------- launch ----------------
extern "C" void kernel_launch(void* const* d_in, const int* in_sizes, int n_in,
                              void* d_out, int out_size) {
    const float* x   = (const float*)d_in[0];
    const int*   hei = (const int*)d_in[1];
    const int*   nidx = hei;
    const int*   eidx = hei + NNZ;
    const float* W1 = (const float*)d_in[2];
    const float* b1 = (const float*)d_in[3];
    const float* W2 = (const float*)d_in[4];
    const float* b2 = (const float*)d_in[5];
    const float* W3 = (const float*)d_in[6];
    const float* b3 = (const float*)d_in[7];
    const float* aw = (const float*)d_in[8];
    const float* ab = (const float*)d_in[9];
    float* out = (float*)d_out;

    static __half *p_xh = nullptr, *p_xwE, *p_h16, *p_h16b;
    static float *p_t, *p_s, *p_c, *p_cdot;
    static float *p_binv, *p_dinv, *p_logits, *p_sumexp;
    static int *p_deg_e, *p_deg_n, *p_off_e, *p_off_n, *p_cur_e, *p_cur_n, *p_csr_e, *p_csr_n;
    static int *p_bsum_e, *p_bsum_n;
    static unsigned int* p_maxbits;
    static __nv_bfloat16 *p_Apk, *p_Wpk;
    static CUtensorMap tmA, tmB1, tmB2, tmB3;
    static cudaStream_t s1;
    static cudaEvent_t evFork, evCnt, evPrep, evN;
    if (!p_xh) {
        cudaGetSymbolAddress((void**)&p_xh, g_xh);
        cudaGetSymbolAddress((void**)&p_xwE, g_xwE);
        cudaGetSymbolAddress((void**)&p_h16, g_h16);
        cudaGetSymbolAddress((void**)&p_h16b, g_h16b);
        cudaGetSymbolAddress((void**)&p_t, g_t);
        cudaGetSymbolAddress((void**)&p_s, g_s);
        cudaGetSymbolAddress((void**)&p_c, g_c);
        cudaGetSymbolAddress((void**)&p_cdot, g_cdot);
        cudaGetSymbolAddress((void**)&p_binv, g_binv);
        cudaGetSymbolAddress((void**)&p_dinv, g_dinv);
        cudaGetSymbolAddress((void**)&p_logits, g_logits);
        cudaGetSymbolAddress((void**)&p_sumexp, g_sumexp);
        cudaGetSymbolAddress((void**)&p_deg_e, g_deg_e);
        cudaGetSymbolAddress((void**)&p_deg_n, g_deg_n);
        cudaGetSymbolAddress((void**)&p_off_e, g_off_e);
        cudaGetSymbolAddress((void**)&p_off_n, g_off_n);
        cudaGetSymbolAddress((void**)&p_cur_e, g_cur_e);
        cudaGetSymbolAddress((void**)&p_cur_n, g_cur_n);
        cudaGetSymbolAddress((void**)&p_csr_e, g_csr_e);
        cudaGetSymbolAddress((void**)&p_csr_n, g_csr_n);
        cudaGetSymbolAddress((void**)&p_bsum_e, g_bsum_e);
        cudaGetSymbolAddress((void**)&p_bsum_n, g_bsum_n);
        cudaGetSymbolAddress((void**)&p_maxbits, g_maxbits);
        cudaGetSymbolAddress((void**)&p_Apk, g_Apk);
        cudaGetSymbolAddress((void**)&p_Wpk, g_Wpk);
        cudaFuncSetAttribute(k_mma_gemm, cudaFuncAttributeMaxDynamicSharedMemorySize, SMEM_GEMM);
        cudaStreamCreateWithFlags(&s1, cudaStreamNonBlocking);
        cudaEventCreateWithFlags(&evFork, cudaEventDisableTiming);
        cudaEventCreateWithFlags(&evCnt, cudaEventDisableTiming);
        cudaEventCreateWithFlags(&evPrep, cudaEventDisableTiming);
        cudaEventCreateWithFlags(&evN, cudaEventDisableTiming);

        void* fp = nullptr;
        cudaDriverEntryPointQueryResult qr;
        cudaGetDriverEntryPoint("cuTensorMapEncodeTiled", &fp, cudaEnableDefault, &qr);
        PFN_encodeTmap enc = (PFN_encodeTmap)fp;
        unsigned long long dimsA[3] = {128ull, (unsigned long long)N_EDGES, (unsigned long long)NCHUNK};
        unsigned long long strA[2]  = {128ull, 128ull * N_EDGES};
        unsigned long long dimsB[3] = {128ull, 512ull, (unsigned long long)NCHUNK};
        unsigned long long strB[2]  = {128ull, 128ull * 512ull};
        unsigned int box[3] = {128u, 128u, 1u};
        unsigned int est[3] = {1u, 1u, 1u};
        enc(&tmA, CU_TENSOR_MAP_DATA_TYPE_UINT8, 3, (void*)p_Apk, dimsA, strA, box, est,
            CU_TENSOR_MAP_INTERLEAVE_NONE, CU_TENSOR_MAP_SWIZZLE_128B,
            CU_TENSOR_MAP_L2_PROMOTION_L2_128B, CU_TENSOR_MAP_FLOAT_OOB_FILL_NONE);
        enc(&tmB1, CU_TENSOR_MAP_DATA_TYPE_UINT8, 3, (void*)(p_Wpk), dimsB, strB, box, est,
            CU_TENSOR_MAP_INTERLEAVE_NONE, CU_TENSOR_MAP_SWIZZLE_128B,
            CU_TENSOR_MAP_L2_PROMOTION_L2_128B, CU_TENSOR_MAP_FLOAT_OOB_FILL_NONE);
        enc(&tmB2, CU_TENSOR_MAP_DATA_TYPE_UINT8, 3, (void*)(p_Wpk + WPK_SLICE), dimsB, strB, box, est,
            CU_TENSOR_MAP_INTERLEAVE_NONE, CU_TENSOR_MAP_SWIZZLE_128B,
            CU_TENSOR_MAP_L2_PROMOTION_L2_128B, CU_TENSOR_MAP_FLOAT_OOB_FILL_NONE);
        enc(&tmB3, CU_TENSOR_MAP_DATA_TYPE_UINT8, 3, (void*)(p_Wpk + 2 * WPK_SLICE), dimsB, strB, box, est,
            CU_TENSOR_MAP_INTERLEAVE_NONE, CU_TENSOR_MAP_SWIZZLE_128B,
            CU_TENSOR_MAP_L2_PROMOTION_L2_128B, CU_TENSOR_MAP_FLOAT_OOB_FILL_NONE);
    }

    // ---- fork: conversions on s1; CSR edge-side on stream 0 ----
    cudaEventRecord(evFork, 0);
    cudaStreamWaitEvent(s1, evFork, 0);
    k_cvtX<<<N_NODES, 320, 0, s1>>>(x, p_xh);
    k_packW<<<256, 320, 0, s1>>>(W1, 300, 256, p_Wpk);
    k_packW<<<256, 320, 0, s1>>>(W2, 256, 256, p_Wpk + WPK_SLICE);
    k_packW<<<128, 320, 0, s1>>>(W3, 256, 128, p_Wpk + 2 * WPK_SLICE);
    k_cdot<<<1, 128, 0, s1>>>(b3, aw, ab, p_cdot);
    cudaEventRecord(evPrep, s1);

    k_zero_meta<<<400, 256>>>(p_deg_e, p_deg_n, p_cur_e, p_cur_n, p_maxbits, p_sumexp, out);
    k_count<<<(NNZ + 255) / 256, 256>>>(nidx, eidx, p_deg_n, p_deg_e);
    cudaEventRecord(evCnt, 0);

    const int NBE = (N_EDGES + 1023) / 1024;
    const int NBN = (N_NODES + 1023) / 1024;
    k_scan_local<<<NBE, 1024>>>(p_deg_e, p_off_e, p_bsum_e, N_EDGES);
    k_carry<<<1, 32>>>(p_bsum_e, NBE, p_off_e + N_EDGES);
    k_scan_add<<<(N_EDGES + 255) / 256, 256>>>(p_off_e, p_bsum_e, p_deg_e, p_binv, N_EDGES);
    k_fill_e<<<(NNZ + 255) / 256, 256>>>(nidx, eidx, p_off_e, p_cur_e, p_csr_e);

    cudaStreamWaitEvent(s1, evCnt, 0);
    k_scan_local<<<NBN, 1024, 0, s1>>>(p_deg_n, p_off_n, p_bsum_n, N_NODES);
    k_carry<<<1, 32, 0, s1>>>(p_bsum_n, NBN, p_off_n + N_NODES);
    k_scan_add<<<(N_NODES + 255) / 256, 256, 0, s1>>>(p_off_n, p_bsum_n, p_deg_n, p_dinv, N_NODES);
    k_fill_n<<<(NNZ + 255) / 256, 256, 0, s1>>>(nidx, eidx, p_off_n, p_cur_n, p_csr_n);
    cudaEventRecord(evN, s1);

    cudaStreamWaitEvent(0, evPrep, 0);

    const int EB = (N_EDGES * 32) / 256;    // 2500
    const int NB = (N_NODES * 32) / 256;    // 12500
    const int GM = (N_EDGES + 127) / 128;   // 157

    // ---- layer 1 ----
    k_edge_pack320<<<EB, 256>>>(p_xh, p_off_e, p_csr_e, p_binv, p_Apk);
    k_mma_gemm<<<dim3(2, GM), 256, SMEM_GEMM>>>(tmA, tmB1, p_xwE, N_EDGES, 256, 5);
    cudaStreamWaitEvent(0, evN, 0);
    k_node_agg256<<<NB, 256>>>(p_xwE, p_off_n, p_csr_n, p_dinv, b1, p_h16);

    // ---- layer 2 ----
    k_edge_pack256<<<EB, 256>>>(p_h16, p_off_e, p_csr_e, p_binv, p_Apk);
    k_mma_gemm<<<dim3(2, GM), 256, SMEM_GEMM>>>(tmA, tmB2, p_xwE, N_EDGES, 256, 4);
    k_node_agg256<<<NB, 256>>>(p_xwE, p_off_n, p_csr_n, p_dinv, b2, p_h16b);

    // ---- layer 3: edge GEMM then algebraic pooling tail ----
    k_edge_pack256<<<EB, 256>>>(p_h16b, p_off_e, p_csr_e, p_binv, p_Apk);
    k_mma_gemm<<<dim3(1, GM), 256, SMEM_GEMM>>>(tmA, tmB3, p_xwE, N_EDGES, 128, 4);
    k_edge_dot<<<EB, 256>>>(p_xwE, aw, p_t);
    k_logits_node<<<(N_NODES + 255) / 256, 256>>>(p_t, p_off_n, p_csr_n, p_dinv, p_cdot,
                                                  p_logits, p_maxbits);
    k_sumexp_coef<<<512, 256>>>(p_logits, p_maxbits, p_dinv, p_c, p_sumexp);
    k_edge_coef<<<EB, 256>>>(p_c, p_off_e, p_csr_e, p_s);
    k_final_sum<<<GM, 128>>>(p_xwE, p_s, out);
    k_finalize<<<1, 128>>>(out, p_sumexp, b3);
}